// round 6
// baseline (speedup 1.0000x reference)
#include <cuda_runtime.h>
#include <cuda_bf16.h>
#include <math.h>

#define NB 32
#define CH 16
#define G  256
#define GG (G*G)

#define XSTR 40                     // bf16 per pixel in smem (80B, conflict-free ldmatrix)
#define BSTR 40
#define TI   16                     // output tile 16x16
#define TH   18                     // tile + halo
#define XEL2 (TH*TH*XSTR)           // 12960 bf16 per split
#define BROWS (9*2*32)              // 576 weight rows
#define SMEM_MMA ((2*XEL2 + BROWS*BSTR) * 2)   // 97,920 B

typedef unsigned int u32;

// ---------------- scratch (device globals: allocation-free) ----------------
__device__ float  g_rhat[NB*GG];
__device__ float2 g_c1[NB*GG];
__device__ float2 g_c2[NB*GG];
__device__ __nv_bfloat16 g_Ahi[(size_t)NB*GG*32];
__device__ __nv_bfloat16 g_Alo[(size_t)NB*GG*32];
__device__ __nv_bfloat16 g_Bhi[(size_t)NB*GG*32];
__device__ __nv_bfloat16 g_Blo[(size_t)NB*GG*32];
__device__ __nv_bfloat16 g_Bw[4*NB*BROWS*32];     // precomputed weight mats [layer][b][tap*2+hl][n][k]

// ---------------- helpers ----------------
__device__ __forceinline__ u32 sptr(const void* p) {
    return (u32)__cvta_generic_to_shared(p);
}
__device__ __forceinline__ void ldmat4(u32* r, u32 addr) {
    asm volatile("ldmatrix.sync.aligned.m8n8.x4.shared.b16 {%0,%1,%2,%3}, [%4];"
        : "=r"(r[0]), "=r"(r[1]), "=r"(r[2]), "=r"(r[3]) : "r"(addr));
}
__device__ __forceinline__ void mma_bf16(float* d, const u32* a, const u32* b) {
    asm volatile("mma.sync.aligned.m16n8k16.row.col.f32.bf16.bf16.f32 "
        "{%0,%1,%2,%3}, {%4,%5,%6,%7}, {%8,%9}, {%0,%1,%2,%3};"
        : "+f"(d[0]), "+f"(d[1]), "+f"(d[2]), "+f"(d[3])
        : "r"(a[0]), "r"(a[1]), "r"(a[2]), "r"(a[3]), "r"(b[0]), "r"(b[1]));
}
__device__ __forceinline__ u32 pack_split(float a, float b, u32& lo_out) {
    __nv_bfloat16 ha = __float2bfloat16(a);
    __nv_bfloat16 hb = __float2bfloat16(b);
    float ra = a - __bfloat162float(ha);
    float rb = b - __bfloat162float(hb);
    __nv_bfloat162 H; H.x = ha; H.y = hb;
    __nv_bfloat162 L; L.x = __float2bfloat16(ra); L.y = __float2bfloat16(rb);
    lo_out = *(u32*)&L;
    return *(u32*)&H;
}
__device__ __forceinline__ int Lperm(int n) {
    return ((n & 7) >> 1) * 8 + ((n >> 3) << 1) + (n & 1);
}

// ---------------- 256-pt Stockham radix-2 FFT ----------------
__device__ __forceinline__ void fft256_block(float2* s0, float2* s1, int t, float dir)
{
    float2* src = s0; float2* dst = s1;
#pragma unroll
    for (int s = 0; s < 8; s++) {
        int Ns = 1 << s;
        int jm = t & (Ns - 1);
        float2 a = src[t];
        float2 b = src[t + 128];
        float ang = dir * 3.14159265358979323846f * (float)jm / (float)Ns;
        float sn, cs;
        __sincosf(ang, &sn, &cs);
        float2 bt = make_float2(b.x*cs - b.y*sn, b.x*sn + b.y*cs);
        int id = ((t >> s) << (s + 1)) | jm;
        dst[id]      = make_float2(a.x + bt.x, a.y + bt.y);
        dst[id + Ns] = make_float2(a.x - bt.x, a.y - bt.y);
        __syncthreads();
        float2* tt = src; src = dst; dst = tt;
    }
}

// ---------------- ifft2 of rsym, pass A ----------------
__global__ void ifft_passA_kernel(const float* __restrict__ r)
{
    __shared__ float2 bA[256], bB[256];
    const int m = blockIdx.x, b = blockIdx.y, t = threadIdx.x;

    if (m == 0 || m == 128) {
        g_c1[(size_t)b*GG + (size_t)t*256 + m]        = make_float2(0.f, 0.f);
        g_c1[(size_t)b*GG + (size_t)(t+128)*256 + m]  = make_float2(0.f, 0.f);
        return;
    }
    const float sm = (m < 128) ? 1.f : -1.f;
    const int   im = (m < 128) ? (m - 1) : (255 - m);
    const float* rrow = r + ((size_t)b*127 + im)*127;

#pragma unroll
    for (int k = 0; k < 2; k++) {
        int n = t + k*128;
        float v = 0.f;
        if (n != 0 && n != 128)
            v = (n < 128) ? rrow[n-1] : -rrow[255-n];
        bA[n] = make_float2(sm * v, 0.f);
    }
    __syncthreads();
    fft256_block(bA, bB, t, +1.0f);
    const float sc = 1.0f / 256.0f;
    for (int k = t; k < 256; k += 128) {
        float2 v = bA[k];
        g_c1[(size_t)b*GG + (size_t)((k+128)&255)*256 + m] = make_float2(v.x*sc, v.y*sc);
    }
}

// ---------------- ifft2 pass B ----------------
__global__ void ifft_passB_kernel()
{
    __shared__ float2 bA[256], bB[256];
    const int vp = blockIdx.x, b = blockIdx.y, t = threadIdx.x;
    const size_t base = (size_t)b*GG + (size_t)vp*256;
    bA[t]     = g_c1[base + t];
    bA[t+128] = g_c1[base + t + 128];
    __syncthreads();
    fft256_block(bA, bB, t, +1.0f);
    const float sc = 1.0f / 256.0f;
    for (int u = t; u < 256; u += 128)
        g_rhat[(size_t)b*GG + (size_t)((u+128)&255)*256 + vp] = bA[u].x * sc;
}

// ---------------- weight precompute: 4 layer-variants -> g_Bw ----------------
__global__ void wprep_kernel(const float* __restrict__ w2r, const float* __restrict__ w2i,
                             const float* __restrict__ w3r, const float* __restrict__ w3i)
{
    const int b = blockIdx.x, layer = blockIdx.y, tid = threadIdx.x;
    const float *wr, *wi; bool adj;
    if      (layer == 0) { wr = w2r; wi = w2i; adj = false; }
    else if (layer == 1) { wr = w3r; wi = w3i; adj = false; }
    else if (layer == 2) { wr = w3r; wi = w3i; adj = true;  }
    else                 { wr = w2r; wi = w2i; adj = true;  }
    __nv_bfloat16* dst = g_Bw + ((size_t)(layer*NB + b))*BROWS*32;

    for (int idx = tid; idx < 9*32*32; idx += 256) {
        int tap = idx >> 10;
        int n = (idx >> 5) & 31;
        int k = idx & 31;
        int dy = tap/3, dx = tap - 3*dy;
        int cn = Lperm(n);
        int co = cn & 15, ci = k & 15;
        float vr, vi;
        if (!adj) { int off = ((b*CH + co)*CH + ci)*9 + dy*3 + dx; vr = wr[off]; vi = wi[off]; }
        else      { int off = ((b*CH + ci)*CH + co)*9 + dx*3 + dy; vr = wr[off]; vi = -wi[off]; }
        float v = (cn < 16) ? ((k < 16) ? vr : -vi)
                            : ((k < 16) ? vi :  vr);
        __nv_bfloat16 h = __float2bfloat16(v);
        __nv_bfloat16 l = __float2bfloat16(v - __bfloat162float(h));
        dst[((tap*2 + 0)*32 + n)*32 + k] = h;
        dst[((tap*2 + 1)*32 + n)*32 + k] = l;
    }
}

// ---------------- conv1: real r_hat x complex w1 -> act bufs ----------------
__global__ void __launch_bounds__(256, 2) conv1_kernel(
    const float* __restrict__ w1r, const float* __restrict__ w1i,
    __nv_bfloat16* __restrict__ out_hi, __nv_bfloat16* __restrict__ out_lo)
{
    __shared__ float  sX[34*34];
    __shared__ float2 sW[CH*9];
    const int b  = blockIdx.z;
    const int ox0 = blockIdx.x*32, oy0 = blockIdx.y*32;
    const int tid = threadIdx.x;

    for (int idx = tid; idx < 34*34; idx += 256) {
        int yy = idx / 34, xx = idx - yy*34;
        int gy = oy0 + yy - 1, gx = ox0 + xx - 1;
        float v = 0.f;
        if ((unsigned)gy < 256u && (unsigned)gx < 256u)
            v = g_rhat[(size_t)b*GG + gy*256 + gx];
        sX[idx] = v;
    }
    if (tid < CH*9) {
        int off = b*(CH*9) + tid;
        sW[tid] = make_float2(w1r[off], w1i[off]);
    }
    __syncthreads();

    const int qx = tid & 15, qy = tid >> 4;
    const int px0 = qx*2, py0 = qy*2;
    float p[4][4];
#pragma unroll
    for (int yy = 0; yy < 4; yy++)
#pragma unroll
        for (int xx = 0; xx < 4; xx++)
            p[yy][xx] = sX[(py0+yy)*34 + px0+xx];

#pragma unroll 1
    for (int half = 0; half < 2; half++) {
        float ar[8][4], ai[8][4];
#pragma unroll
        for (int c = 0; c < 8; c++)
#pragma unroll
            for (int q = 0; q < 4; q++) { ar[c][q] = 0.f; ai[c][q] = 0.f; }

#pragma unroll
        for (int k = 0; k < 9; k++) {
            int dy = k/3, dx = k - dy*3;
#pragma unroll
            for (int c = 0; c < 8; c++) {
                float2 w = sW[(half*8 + c)*9 + k];
#pragma unroll
                for (int iy = 0; iy < 2; iy++)
#pragma unroll
                    for (int ix = 0; ix < 2; ix++) {
                        float x = p[dy+iy][dx+ix];
                        ar[c][iy*2+ix] = fmaf(w.x, x, ar[c][iy*2+ix]);
                        ai[c][iy*2+ix] = fmaf(w.y, x, ai[c][iy*2+ix]);
                    }
            }
        }
#pragma unroll
        for (int iy = 0; iy < 2; iy++)
#pragma unroll
            for (int ix = 0; ix < 2; ix++) {
                int y = oy0 + py0 + iy;
                int x = ox0 + px0 + ix;
                size_t pb = (((size_t)b*256 + y)*256 + x)*32;
                u32 rh[4], rl[4], ih[4], il[4];
#pragma unroll
                for (int j = 0; j < 4; j++) {
                    rh[j] = pack_split(ar[2*j][iy*2+ix], ar[2*j+1][iy*2+ix], rl[j]);
                    ih[j] = pack_split(ai[2*j][iy*2+ix], ai[2*j+1][iy*2+ix], il[j]);
                }
                *(uint4*)(out_hi + pb + half*8)      = make_uint4(rh[0],rh[1],rh[2],rh[3]);
                *(uint4*)(out_hi + pb + 16 + half*8) = make_uint4(ih[0],ih[1],ih[2],ih[3]);
                *(uint4*)(out_lo + pb + half*8)      = make_uint4(rl[0],rl[1],rl[2],rl[3]);
                *(uint4*)(out_lo + pb + 16 + half*8) = make_uint4(il[0],il[1],il[2],il[3]);
            }
    }
}

// ---------------- main complex 16->16 conv via mma.sync, 16x16 tile, 2 CTAs/SM ----------------
template<bool WT>
__global__ void __launch_bounds__(256, 2) conv16_mma(
    const __nv_bfloat16* __restrict__ in_hi, const __nv_bfloat16* __restrict__ in_lo,
    __nv_bfloat16* __restrict__ out_hi, __nv_bfloat16* __restrict__ out_lo,
    const __nv_bfloat16* __restrict__ Bw_base, int layer,
    const float* __restrict__ wtr, const float* __restrict__ wti)
{
    extern __shared__ __nv_bfloat16 sm[];
    __nv_bfloat16* sXhi = sm;
    __nv_bfloat16* sXlo = sm + XEL2;
    __nv_bfloat16* sB   = sm + 2*XEL2;      // [row 576][BSTR]

    const int b = blockIdx.z;
    const int ox0 = blockIdx.x*TI, oy0 = blockIdx.y*TI;
    const int tid = threadIdx.x;

    // ---- stage precomputed weights (576 rows of 32 bf16 = 4 uint4 each) ----
    {
        const uint4* src = (const uint4*)(Bw_base + ((size_t)(layer*NB + b))*BROWS*32);
        for (int idx = tid; idx < BROWS*4; idx += 256) {
            int row = idx >> 2, j = idx & 3;
            *(uint4*)(sB + row*BSTR + j*8) = src[idx];
        }
    }
    // ---- stage input tile 18x18 ----
    for (int p = tid; p < TH*TH; p += 256) {
        int yy = p/TH, xx = p - TH*yy;
        int gy = oy0 + yy - 1, gx = ox0 + xx - 1;
        uint4 vh[4], vl[4];
        if ((unsigned)gy < 256u && (unsigned)gx < 256u) {
            size_t pb = (((size_t)b*256 + gy)*256 + gx)*32;
            const uint4* ph = (const uint4*)(in_hi + pb);
            const uint4* pl = (const uint4*)(in_lo + pb);
#pragma unroll
            for (int j = 0; j < 4; j++) { vh[j] = ph[j]; vl[j] = pl[j]; }
        } else {
            uint4 z = make_uint4(0,0,0,0);
#pragma unroll
            for (int j = 0; j < 4; j++) { vh[j] = z; vl[j] = z; }
        }
        uint4* dh = (uint4*)(sXhi + p*XSTR);
        uint4* dl = (uint4*)(sXlo + p*XSTR);
#pragma unroll
        for (int j = 0; j < 4; j++) { dh[j] = vh[j]; dl[j] = vl[j]; }
    }
    __syncthreads();

    const int w = tid >> 5, lane = tid & 31;
    const int mrow = ((lane>>3)&1)*8 + (lane&7);
    const int kofs = ((lane>>4)&1)*8;
    const u32 xhiB = sptr(sXhi), xloB = sptr(sXlo);
    const u32 sBB = sptr(sB);
    const u32 bLaneOff = ((lane & 7)*BSTR + (lane >> 3)*8) * 2;

    float acc[2][4][4];
#pragma unroll
    for (int mt = 0; mt < 2; mt++)
#pragma unroll
        for (int f = 0; f < 4; f++)
#pragma unroll
            for (int j = 0; j < 4; j++) acc[mt][f][j] = 0.f;

#pragma unroll 1
    for (int tap = 0; tap < 9; tap++) {
        int dy = tap/3, dx = tap - 3*dy;
        u32 bhi[2][4][2], blo[2][4][2];
#pragma unroll
        for (int f = 0; f < 4; f++) {
            u32 r[4];
            ldmat4(r, sBB + ((tap*2+0)*32 + f*8)*BSTR*2 + bLaneOff);
            bhi[0][f][0] = r[0]; bhi[0][f][1] = r[1];
            bhi[1][f][0] = r[2]; bhi[1][f][1] = r[3];
            ldmat4(r, sBB + ((tap*2+1)*32 + f*8)*BSTR*2 + bLaneOff);
            blo[0][f][0] = r[0]; blo[0][f][1] = r[1];
            blo[1][f][0] = r[2]; blo[1][f][1] = r[3];
        }
#pragma unroll
        for (int mt = 0; mt < 2; mt++) {
            int sy = w*2 + mt + dy;
            int sx = mrow + dx;
            u32 off = ((sy*TH + sx)*XSTR + kofs)*2;
#pragma unroll
            for (int k16 = 0; k16 < 2; k16++) {
                u32 ah[4], al[4];
                ldmat4(ah, xhiB + off + k16*32);
                ldmat4(al, xloB + off + k16*32);
#pragma unroll
                for (int f = 0; f < 4; f++) mma_bf16(acc[mt][f], ah, bhi[k16][f]);
#pragma unroll
                for (int f = 0; f < 4; f++) mma_bf16(acc[mt][f], ah, blo[k16][f]);
#pragma unroll
                for (int f = 0; f < 4; f++) mma_bf16(acc[mt][f], al, bhi[k16][f]);
            }
        }
    }

    // ---- epilogue ----
    const int rA = lane >> 2;
    const int q  = lane & 3;
    const bool isRe = (q < 2);
#pragma unroll
    for (int mt = 0; mt < 2; mt++) {
        int y = oy0 + w*2 + mt;
#pragma unroll
        for (int half = 0; half < 2; half++) {
            int x = ox0 + rA + half*8;
            size_t pb = (((size_t)b*256 + y)*256 + x)*32;
            if (!WT) {
                u32 h4[4], l4[4];
#pragma unroll
                for (int f = 0; f < 4; f++)
                    h4[f] = pack_split(acc[mt][f][half*2+0], acc[mt][f][half*2+1], l4[f]);
                *(uint4*)(out_hi + pb + q*8) = make_uint4(h4[0],h4[1],h4[2],h4[3]);
                *(uint4*)(out_lo + pb + q*8) = make_uint4(l4[0],l4[1],l4[2],l4[3]);
            } else {
                size_t wbase = (size_t)b*16*GG + (size_t)y*256 + x;
                u32 h4[4], l4[4];
#pragma unroll
                for (int f = 0; f < 4; f++) {
                    float o2[2];
#pragma unroll
                    for (int j = 0; j < 2; j++) {
                        float my = acc[mt][f][half*2+j];
                        float prt = __shfl_xor_sync(0xffffffffu, my, 2);
                        int c = (q & 1)*8 + 2*f + j;
                        float wre = wtr[wbase + (size_t)c*GG];
                        float wim = wti[wbase + (size_t)c*GG];
                        o2[j] = isRe ? (my*wre - prt*wim) : (my*wre + prt*wim);
                    }
                    h4[f] = pack_split(o2[0], o2[1], l4[f]);
                }
                *(uint4*)(out_hi + pb + q*8) = make_uint4(h4[0],h4[1],h4[2],h4[3]);
                *(uint4*)(out_lo + pb + q*8) = make_uint4(l4[0],l4[1],l4[2],l4[3]);
            }
        }
    }
}

// ---------------- conv 16->1 with adj(w1), writes g_c1 ----------------
__global__ void __launch_bounds__(256, 1) conv_adj1_kernel(
    const __nv_bfloat16* __restrict__ in_hi, const __nv_bfloat16* __restrict__ in_lo,
    const float* __restrict__ w1r, const float* __restrict__ w1i)
{
    extern __shared__ float2 dynS[];
    float2* sIn = dynS;
    __shared__ float2 sW[CH*9];
    const int b  = blockIdx.z;
    const int ox0 = blockIdx.x*32, oy0 = blockIdx.y*32;
    const int tid = threadIdx.x;

    if (tid < CH*9) {
        int ci = tid / 9, k = tid % 9;
        int dy = k/3, dx = k - dy*3;
        int off = (b*CH + ci)*9 + dx*3 + dy;
        sW[tid] = make_float2(w1r[off], -w1i[off]);
    }
    for (int p = tid; p < 34*34; p += 256) {
        int yy = p/34, xx = p - 34*yy;
        int gy = oy0 + yy - 1, gx = ox0 + xx - 1;
        float2 vals[16];
        if ((unsigned)gy < 256u && (unsigned)gx < 256u) {
            size_t pb = (((size_t)b*256 + gy)*256 + gx)*32;
            uint4 hv[4], lv[4];
            const uint4* ph = (const uint4*)(in_hi + pb);
            const uint4* pl = (const uint4*)(in_lo + pb);
#pragma unroll
            for (int j = 0; j < 4; j++) { hv[j] = ph[j]; lv[j] = pl[j]; }
            const __nv_bfloat16* hb = (const __nv_bfloat16*)hv;
            const __nv_bfloat16* lb = (const __nv_bfloat16*)lv;
#pragma unroll
            for (int ci = 0; ci < 16; ci++) {
                float re = __bfloat162float(hb[ci])    + __bfloat162float(lb[ci]);
                float im = __bfloat162float(hb[ci+16]) + __bfloat162float(lb[ci+16]);
                vals[ci] = make_float2(re, im);
            }
        } else {
#pragma unroll
            for (int ci = 0; ci < 16; ci++) vals[ci] = make_float2(0.f, 0.f);
        }
#pragma unroll
        for (int ci = 0; ci < 16; ci++)
            sIn[ci*(34*34) + p] = vals[ci];
    }
    __syncthreads();

    const int qx = tid & 15, qy = tid >> 4;
    const int px0 = qx*2, py0 = qy*2;
    float ar[4] = {0.f,0.f,0.f,0.f}, ai[4] = {0.f,0.f,0.f,0.f};

#pragma unroll 1
    for (int ci = 0; ci < CH; ci++) {
        float2 p[4][4];
        const float2* base = sIn + ci*(34*34) + py0*34 + px0;
#pragma unroll
        for (int yy = 0; yy < 4; yy++)
#pragma unroll
            for (int xx = 0; xx < 4; xx++)
                p[yy][xx] = base[yy*34 + xx];
#pragma unroll
        for (int k = 0; k < 9; k++) {
            int dy = k/3, dx = k - dy*3;
            float2 w = sW[ci*9 + k];
#pragma unroll
            for (int iy = 0; iy < 2; iy++)
#pragma unroll
                for (int ix = 0; ix < 2; ix++) {
                    float2 x = p[dy+iy][dx+ix];
                    ar[iy*2+ix] = fmaf(w.x, x.x, fmaf(-w.y, x.y, ar[iy*2+ix]));
                    ai[iy*2+ix] = fmaf(w.x, x.y, fmaf( w.y, x.x, ai[iy*2+ix]));
                }
        }
    }
#pragma unroll
    for (int iy = 0; iy < 2; iy++) {
        int oy = oy0 + py0 + iy;
        int ox = ox0 + px0;
        *(float4*)(g_c1 + (size_t)b*GG + (size_t)oy*256 + ox) =
            make_float4(ar[iy*2+0], ai[iy*2+0], ar[iy*2+1], ai[iy*2+1]);
    }
}

// ---------------- forward fft2 with ifftshift on input ----------------
__global__ void fft_passA_kernel()
{
    __shared__ float2 bA[256], bB[256];
    const int m = blockIdx.x, b = blockIdx.y, t = threadIdx.x;
    const int msrc = (m + 128) & 255;
    const size_t base = (size_t)b*GG + (size_t)msrc*256;
    for (int k = t; k < 256; k += 128)
        bA[k] = g_c1[base + ((k + 128) & 255)];
    __syncthreads();
    fft256_block(bA, bB, t, -1.0f);
    for (int q = t; q < 256; q += 128)
        g_c2[(size_t)b*GG + (size_t)q*256 + m] = bA[q];
}

__global__ void fft_passB_kernel(float* __restrict__ out)
{
    __shared__ float2 bA[256], bB[256];
    const int q = blockIdx.x, b = blockIdx.y, t = threadIdx.x;
    const size_t base = (size_t)b*GG + (size_t)q*256;
    bA[t]     = g_c2[base + t];
    bA[t+128] = g_c2[base + t + 128];
    __syncthreads();
    fft256_block(bA, bB, t, -1.0f);
    for (int p = t; p < 256; p += 128)
        if (p < 127)
            out[((size_t)b*127 + p)*127 + q] = bA[p].x;
}

// ---------------- launch ----------------
extern "C" void kernel_launch(void* const* d_in, const int* in_sizes, int n_in,
                              void* d_out, int out_size)
{
    (void)in_sizes; (void)n_in; (void)out_size;
    const float* r   = (const float*)d_in[0];
    const float* w1r = (const float*)d_in[1];
    const float* w1i = (const float*)d_in[2];
    const float* w2r = (const float*)d_in[3];
    const float* w2i = (const float*)d_in[4];
    const float* w3r = (const float*)d_in[5];
    const float* w3i = (const float*)d_in[6];
    const float* wtr = (const float*)d_in[7];
    const float* wti = (const float*)d_in[8];
    float* out = (float*)d_out;

    void *pAh, *pAl, *pBh, *pBl, *pBw;
    cudaGetSymbolAddress(&pAh, g_Ahi);
    cudaGetSymbolAddress(&pAl, g_Alo);
    cudaGetSymbolAddress(&pBh, g_Bhi);
    cudaGetSymbolAddress(&pBl, g_Blo);
    cudaGetSymbolAddress(&pBw, g_Bw);
    __nv_bfloat16* Ah = (__nv_bfloat16*)pAh;
    __nv_bfloat16* Al = (__nv_bfloat16*)pAl;
    __nv_bfloat16* Bh = (__nv_bfloat16*)pBh;
    __nv_bfloat16* Bl = (__nv_bfloat16*)pBl;
    __nv_bfloat16* Bw = (__nv_bfloat16*)pBw;

    const int SMEMA1 = CH*34*34*(int)sizeof(float2);
    cudaFuncSetAttribute(conv16_mma<false>, cudaFuncAttributeMaxDynamicSharedMemorySize, SMEM_MMA);
    cudaFuncSetAttribute(conv16_mma<true >, cudaFuncAttributeMaxDynamicSharedMemorySize, SMEM_MMA);
    cudaFuncSetAttribute(conv_adj1_kernel,  cudaFuncAttributeMaxDynamicSharedMemorySize, SMEMA1);

    dim3 gfft(256, NB);
    ifft_passA_kernel<<<gfft, 128>>>(r);

    dim3 gwp(NB, 4);
    wprep_kernel<<<gwp, 256>>>(w2r, w2i, w3r, w3i);

    ifft_passB_kernel<<<gfft, 128>>>();

    dim3 gc1(8, 8, NB);
    conv1_kernel<<<gc1, 256>>>(w1r, w1i, Ah, Al);

    dim3 gconv(16, 16, NB);
    conv16_mma<false><<<gconv, 256, SMEM_MMA>>>(Ah, Al, Bh, Bl, Bw, 0, nullptr, nullptr);
    conv16_mma<true ><<<gconv, 256, SMEM_MMA>>>(Bh, Bl, Ah, Al, Bw, 1, wtr, wti);
    conv16_mma<false><<<gconv, 256, SMEM_MMA>>>(Ah, Al, Bh, Bl, Bw, 2, nullptr, nullptr);
    conv16_mma<false><<<gconv, 256, SMEM_MMA>>>(Bh, Bl, Ah, Al, Bw, 3, nullptr, nullptr);
    conv_adj1_kernel<<<gc1, 256, SMEMA1>>>(Ah, Al, w1r, w1i);

    fft_passA_kernel<<<gfft, 128>>>();
    dim3 gfftB(127, NB);
    fft_passB_kernel<<<gfftB, 128>>>(out);
}

// round 7
// speedup vs baseline: 1.0058x; 1.0058x over previous
#include <cuda_runtime.h>
#include <cuda_bf16.h>
#include <math.h>

#define NB 32
#define CH 16
#define G  256
#define GG (G*G)

#define XSTR 40                     // bf16 per pixel in smem (80B, conflict-free ldmatrix)
#define BSTR 40
#define TI   16                     // output tile 16x16
#define TH   18                     // tile + halo
#define XEL2 (TH*TH*XSTR)           // 12960 bf16 per split
#define BROWS (9*2*32)              // 576 weight rows
#define SMEM_MMA ((2*XEL2 + BROWS*BSTR) * 2)   // 97,920 B

typedef unsigned int u32;

// ---------------- scratch (device globals: allocation-free) ----------------
__device__ float  g_rhat[NB*GG];
__device__ float2 g_c1[NB*GG];
__device__ float2 g_c2[NB*GG];
__device__ __nv_bfloat16 g_Ahi[(size_t)NB*GG*32];
__device__ __nv_bfloat16 g_Alo[(size_t)NB*GG*32];
__device__ __nv_bfloat16 g_Bhi[(size_t)NB*GG*32];
__device__ __nv_bfloat16 g_Blo[(size_t)NB*GG*32];
__device__ __nv_bfloat16 g_Bw[4*NB*BROWS*32];     // precomputed weight mats [layer][b][tap*2+hl][n][k]

// ---------------- helpers ----------------
__device__ __forceinline__ u32 sptr(const void* p) {
    return (u32)__cvta_generic_to_shared(p);
}
__device__ __forceinline__ void ldmat4(u32* r, u32 addr) {
    asm volatile("ldmatrix.sync.aligned.m8n8.x4.shared.b16 {%0,%1,%2,%3}, [%4];"
        : "=r"(r[0]), "=r"(r[1]), "=r"(r[2]), "=r"(r[3]) : "r"(addr));
}
__device__ __forceinline__ void mma_bf16(float* d, const u32* a, const u32* b) {
    asm volatile("mma.sync.aligned.m16n8k16.row.col.f32.bf16.bf16.f32 "
        "{%0,%1,%2,%3}, {%4,%5,%6,%7}, {%8,%9}, {%0,%1,%2,%3};"
        : "+f"(d[0]), "+f"(d[1]), "+f"(d[2]), "+f"(d[3])
        : "r"(a[0]), "r"(a[1]), "r"(a[2]), "r"(a[3]), "r"(b[0]), "r"(b[1]));
}
__device__ __forceinline__ u32 pack_split(float a, float b, u32& lo_out) {
    __nv_bfloat16 ha = __float2bfloat16(a);
    __nv_bfloat16 hb = __float2bfloat16(b);
    float ra = a - __bfloat162float(ha);
    float rb = b - __bfloat162float(hb);
    __nv_bfloat162 H; H.x = ha; H.y = hb;
    __nv_bfloat162 L; L.x = __float2bfloat16(ra); L.y = __float2bfloat16(rb);
    lo_out = *(u32*)&L;
    return *(u32*)&H;
}
__device__ __forceinline__ int Lperm(int n) {
    return ((n & 7) >> 1) * 8 + ((n >> 3) << 1) + (n & 1);
}

// ---------------- 256-pt Stockham radix-2 FFT ----------------
__device__ __forceinline__ void fft256_block(float2* s0, float2* s1, int t, float dir)
{
    float2* src = s0; float2* dst = s1;
#pragma unroll
    for (int s = 0; s < 8; s++) {
        int Ns = 1 << s;
        int jm = t & (Ns - 1);
        float2 a = src[t];
        float2 b = src[t + 128];
        float ang = dir * 3.14159265358979323846f * (float)jm / (float)Ns;
        float sn, cs;
        __sincosf(ang, &sn, &cs);
        float2 bt = make_float2(b.x*cs - b.y*sn, b.x*sn + b.y*cs);
        int id = ((t >> s) << (s + 1)) | jm;
        dst[id]      = make_float2(a.x + bt.x, a.y + bt.y);
        dst[id + Ns] = make_float2(a.x - bt.x, a.y - bt.y);
        __syncthreads();
        float2* tt = src; src = dst; dst = tt;
    }
}

// ---------------- ifft2 of rsym, pass A ----------------
__global__ void ifft_passA_kernel(const float* __restrict__ r)
{
    __shared__ float2 bA[256], bB[256];
    const int m = blockIdx.x, b = blockIdx.y, t = threadIdx.x;

    if (m == 0 || m == 128) {
        g_c1[(size_t)b*GG + (size_t)t*256 + m]        = make_float2(0.f, 0.f);
        g_c1[(size_t)b*GG + (size_t)(t+128)*256 + m]  = make_float2(0.f, 0.f);
        return;
    }
    const float sm = (m < 128) ? 1.f : -1.f;
    const int   im = (m < 128) ? (m - 1) : (255 - m);
    const float* rrow = r + ((size_t)b*127 + im)*127;

#pragma unroll
    for (int k = 0; k < 2; k++) {
        int n = t + k*128;
        float v = 0.f;
        if (n != 0 && n != 128)
            v = (n < 128) ? rrow[n-1] : -rrow[255-n];
        bA[n] = make_float2(sm * v, 0.f);
    }
    __syncthreads();
    fft256_block(bA, bB, t, +1.0f);
    const float sc = 1.0f / 256.0f;
    for (int k = t; k < 256; k += 128) {
        float2 v = bA[k];
        g_c1[(size_t)b*GG + (size_t)((k+128)&255)*256 + m] = make_float2(v.x*sc, v.y*sc);
    }
}

// ---------------- ifft2 pass B ----------------
__global__ void ifft_passB_kernel()
{
    __shared__ float2 bA[256], bB[256];
    const int vp = blockIdx.x, b = blockIdx.y, t = threadIdx.x;
    const size_t base = (size_t)b*GG + (size_t)vp*256;
    bA[t]     = g_c1[base + t];
    bA[t+128] = g_c1[base + t + 128];
    __syncthreads();
    fft256_block(bA, bB, t, +1.0f);
    const float sc = 1.0f / 256.0f;
    for (int u = t; u < 256; u += 128)
        g_rhat[(size_t)b*GG + (size_t)((u+128)&255)*256 + vp] = bA[u].x * sc;
}

// ---------------- weight precompute: 4 layer-variants -> g_Bw ----------------
__global__ void wprep_kernel(const float* __restrict__ w2r, const float* __restrict__ w2i,
                             const float* __restrict__ w3r, const float* __restrict__ w3i)
{
    const int b = blockIdx.x, layer = blockIdx.y, tid = threadIdx.x;
    const float *wr, *wi; bool adj;
    if      (layer == 0) { wr = w2r; wi = w2i; adj = false; }
    else if (layer == 1) { wr = w3r; wi = w3i; adj = false; }
    else if (layer == 2) { wr = w3r; wi = w3i; adj = true;  }
    else                 { wr = w2r; wi = w2i; adj = true;  }
    __nv_bfloat16* dst = g_Bw + ((size_t)(layer*NB + b))*BROWS*32;

    for (int idx = tid; idx < 9*32*32; idx += 256) {
        int tap = idx >> 10;
        int n = (idx >> 5) & 31;
        int k = idx & 31;
        int dy = tap/3, dx = tap - 3*dy;
        int cn = Lperm(n);
        int co = cn & 15, ci = k & 15;
        float vr, vi;
        if (!adj) { int off = ((b*CH + co)*CH + ci)*9 + dy*3 + dx; vr = wr[off]; vi = wi[off]; }
        else      { int off = ((b*CH + ci)*CH + co)*9 + dx*3 + dy; vr = wr[off]; vi = -wi[off]; }
        float v = (cn < 16) ? ((k < 16) ? vr : -vi)
                            : ((k < 16) ? vi :  vr);
        __nv_bfloat16 h = __float2bfloat16(v);
        __nv_bfloat16 l = __float2bfloat16(v - __bfloat162float(h));
        dst[((tap*2 + 0)*32 + n)*32 + k] = h;
        dst[((tap*2 + 1)*32 + n)*32 + k] = l;
    }
}

// ---------------- conv1: real r_hat x complex w1 -> act bufs ----------------
__global__ void __launch_bounds__(256, 2) conv1_kernel(
    const float* __restrict__ w1r, const float* __restrict__ w1i,
    __nv_bfloat16* __restrict__ out_hi, __nv_bfloat16* __restrict__ out_lo)
{
    __shared__ float  sX[34*34];
    __shared__ float2 sW[CH*9];
    const int b  = blockIdx.z;
    const int ox0 = blockIdx.x*32, oy0 = blockIdx.y*32;
    const int tid = threadIdx.x;

    for (int idx = tid; idx < 34*34; idx += 256) {
        int yy = idx / 34, xx = idx - yy*34;
        int gy = oy0 + yy - 1, gx = ox0 + xx - 1;
        float v = 0.f;
        if ((unsigned)gy < 256u && (unsigned)gx < 256u)
            v = g_rhat[(size_t)b*GG + gy*256 + gx];
        sX[idx] = v;
    }
    if (tid < CH*9) {
        int off = b*(CH*9) + tid;
        sW[tid] = make_float2(w1r[off], w1i[off]);
    }
    __syncthreads();

    const int qx = tid & 15, qy = tid >> 4;
    const int px0 = qx*2, py0 = qy*2;
    float p[4][4];
#pragma unroll
    for (int yy = 0; yy < 4; yy++)
#pragma unroll
        for (int xx = 0; xx < 4; xx++)
            p[yy][xx] = sX[(py0+yy)*34 + px0+xx];

#pragma unroll 1
    for (int half = 0; half < 2; half++) {
        float ar[8][4], ai[8][4];
#pragma unroll
        for (int c = 0; c < 8; c++)
#pragma unroll
            for (int q = 0; q < 4; q++) { ar[c][q] = 0.f; ai[c][q] = 0.f; }

#pragma unroll
        for (int k = 0; k < 9; k++) {
            int dy = k/3, dx = k - dy*3;
#pragma unroll
            for (int c = 0; c < 8; c++) {
                float2 w = sW[(half*8 + c)*9 + k];
#pragma unroll
                for (int iy = 0; iy < 2; iy++)
#pragma unroll
                    for (int ix = 0; ix < 2; ix++) {
                        float x = p[dy+iy][dx+ix];
                        ar[c][iy*2+ix] = fmaf(w.x, x, ar[c][iy*2+ix]);
                        ai[c][iy*2+ix] = fmaf(w.y, x, ai[c][iy*2+ix]);
                    }
            }
        }
#pragma unroll
        for (int iy = 0; iy < 2; iy++)
#pragma unroll
            for (int ix = 0; ix < 2; ix++) {
                int y = oy0 + py0 + iy;
                int x = ox0 + px0 + ix;
                size_t pb = (((size_t)b*256 + y)*256 + x)*32;
                u32 rh[4], rl[4], ih[4], il[4];
#pragma unroll
                for (int j = 0; j < 4; j++) {
                    rh[j] = pack_split(ar[2*j][iy*2+ix], ar[2*j+1][iy*2+ix], rl[j]);
                    ih[j] = pack_split(ai[2*j][iy*2+ix], ai[2*j+1][iy*2+ix], il[j]);
                }
                *(uint4*)(out_hi + pb + half*8)      = make_uint4(rh[0],rh[1],rh[2],rh[3]);
                *(uint4*)(out_hi + pb + 16 + half*8) = make_uint4(ih[0],ih[1],ih[2],ih[3]);
                *(uint4*)(out_lo + pb + half*8)      = make_uint4(rl[0],rl[1],rl[2],rl[3]);
                *(uint4*)(out_lo + pb + 16 + half*8) = make_uint4(il[0],il[1],il[2],il[3]);
            }
    }
}

// ---------------- main complex 16->16 conv via mma.sync, 16x16 tile, 2 CTAs/SM ----------------
template<bool WT>
__global__ void __launch_bounds__(256, 2) conv16_mma(
    const __nv_bfloat16* __restrict__ in_hi, const __nv_bfloat16* __restrict__ in_lo,
    __nv_bfloat16* __restrict__ out_hi, __nv_bfloat16* __restrict__ out_lo,
    const __nv_bfloat16* __restrict__ Bw_base, int layer,
    const float* __restrict__ wtr, const float* __restrict__ wti)
{
    extern __shared__ __nv_bfloat16 sm[];
    __nv_bfloat16* sXhi = sm;
    __nv_bfloat16* sXlo = sm + XEL2;
    __nv_bfloat16* sB   = sm + 2*XEL2;      // [row 576][BSTR]

    const int b = blockIdx.z;
    const int ox0 = blockIdx.x*TI, oy0 = blockIdx.y*TI;
    const int tid = threadIdx.x;

    // ---- stage precomputed weights (576 rows of 32 bf16 = 4 uint4 each) ----
    {
        const uint4* src = (const uint4*)(Bw_base + ((size_t)(layer*NB + b))*BROWS*32);
        for (int idx = tid; idx < BROWS*4; idx += 256) {
            int row = idx >> 2, j = idx & 3;
            *(uint4*)(sB + row*BSTR + j*8) = src[idx];
        }
    }
    // ---- stage input tile 18x18 ----
    for (int p = tid; p < TH*TH; p += 256) {
        int yy = p/TH, xx = p - TH*yy;
        int gy = oy0 + yy - 1, gx = ox0 + xx - 1;
        uint4 vh[4], vl[4];
        if ((unsigned)gy < 256u && (unsigned)gx < 256u) {
            size_t pb = (((size_t)b*256 + gy)*256 + gx)*32;
            const uint4* ph = (const uint4*)(in_hi + pb);
            const uint4* pl = (const uint4*)(in_lo + pb);
#pragma unroll
            for (int j = 0; j < 4; j++) { vh[j] = ph[j]; vl[j] = pl[j]; }
        } else {
            uint4 z = make_uint4(0,0,0,0);
#pragma unroll
            for (int j = 0; j < 4; j++) { vh[j] = z; vl[j] = z; }
        }
        uint4* dh = (uint4*)(sXhi + p*XSTR);
        uint4* dl = (uint4*)(sXlo + p*XSTR);
#pragma unroll
        for (int j = 0; j < 4; j++) { dh[j] = vh[j]; dl[j] = vl[j]; }
    }
    __syncthreads();

    const int w = tid >> 5, lane = tid & 31;
    const int mrow = ((lane>>3)&1)*8 + (lane&7);
    const int kofs = ((lane>>4)&1)*8;
    const u32 xhiB = sptr(sXhi), xloB = sptr(sXlo);
    const u32 sBB = sptr(sB);
    const u32 bLaneOff = ((lane & 7)*BSTR + (lane >> 3)*8) * 2;

    float acc[2][4][4];
#pragma unroll
    for (int mt = 0; mt < 2; mt++)
#pragma unroll
        for (int f = 0; f < 4; f++)
#pragma unroll
            for (int j = 0; j < 4; j++) acc[mt][f][j] = 0.f;

#pragma unroll 1
    for (int tap = 0; tap < 9; tap++) {
        int dy = tap/3, dx = tap - 3*dy;
        u32 bhi[2][4][2], blo[2][4][2];
#pragma unroll
        for (int f = 0; f < 4; f++) {
            u32 r[4];
            ldmat4(r, sBB + ((tap*2+0)*32 + f*8)*BSTR*2 + bLaneOff);
            bhi[0][f][0] = r[0]; bhi[0][f][1] = r[1];
            bhi[1][f][0] = r[2]; bhi[1][f][1] = r[3];
            ldmat4(r, sBB + ((tap*2+1)*32 + f*8)*BSTR*2 + bLaneOff);
            blo[0][f][0] = r[0]; blo[0][f][1] = r[1];
            blo[1][f][0] = r[2]; blo[1][f][1] = r[3];
        }
#pragma unroll
        for (int mt = 0; mt < 2; mt++) {
            int sy = w*2 + mt + dy;
            int sx = mrow + dx;
            u32 off = ((sy*TH + sx)*XSTR + kofs)*2;
#pragma unroll
            for (int k16 = 0; k16 < 2; k16++) {
                u32 ah[4], al[4];
                ldmat4(ah, xhiB + off + k16*32);
                ldmat4(al, xloB + off + k16*32);
#pragma unroll
                for (int f = 0; f < 4; f++) mma_bf16(acc[mt][f], ah, bhi[k16][f]);
#pragma unroll
                for (int f = 0; f < 4; f++) mma_bf16(acc[mt][f], ah, blo[k16][f]);
#pragma unroll
                for (int f = 0; f < 4; f++) mma_bf16(acc[mt][f], al, bhi[k16][f]);
            }
        }
    }

    // ---- epilogue ----
    const int rA = lane >> 2;
    const int q  = lane & 3;
    const bool isRe = (q < 2);
#pragma unroll
    for (int mt = 0; mt < 2; mt++) {
        int y = oy0 + w*2 + mt;
#pragma unroll
        for (int half = 0; half < 2; half++) {
            int x = ox0 + rA + half*8;
            size_t pb = (((size_t)b*256 + y)*256 + x)*32;
            if (!WT) {
                u32 h4[4], l4[4];
#pragma unroll
                for (int f = 0; f < 4; f++)
                    h4[f] = pack_split(acc[mt][f][half*2+0], acc[mt][f][half*2+1], l4[f]);
                *(uint4*)(out_hi + pb + q*8) = make_uint4(h4[0],h4[1],h4[2],h4[3]);
                *(uint4*)(out_lo + pb + q*8) = make_uint4(l4[0],l4[1],l4[2],l4[3]);
            } else {
                size_t wbase = (size_t)b*16*GG + (size_t)y*256 + x;
                u32 h4[4], l4[4];
#pragma unroll
                for (int f = 0; f < 4; f++) {
                    float o2[2];
#pragma unroll
                    for (int j = 0; j < 2; j++) {
                        float my = acc[mt][f][half*2+j];
                        float prt = __shfl_xor_sync(0xffffffffu, my, 2);
                        int c = (q & 1)*8 + 2*f + j;
                        float wre = wtr[wbase + (size_t)c*GG];
                        float wim = wti[wbase + (size_t)c*GG];
                        o2[j] = isRe ? (my*wre - prt*wim) : (my*wre + prt*wim);
                    }
                    h4[f] = pack_split(o2[0], o2[1], l4[f]);
                }
                *(uint4*)(out_hi + pb + q*8) = make_uint4(h4[0],h4[1],h4[2],h4[3]);
                *(uint4*)(out_lo + pb + q*8) = make_uint4(l4[0],l4[1],l4[2],l4[3]);
            }
        }
    }
}

// ---------------- conv 16->1 with adj(w1), writes g_c1 ----------------
__global__ void __launch_bounds__(256, 1) conv_adj1_kernel(
    const __nv_bfloat16* __restrict__ in_hi, const __nv_bfloat16* __restrict__ in_lo,
    const float* __restrict__ w1r, const float* __restrict__ w1i)
{
    extern __shared__ float2 dynS[];
    float2* sIn = dynS;
    __shared__ float2 sW[CH*9];
    const int b  = blockIdx.z;
    const int ox0 = blockIdx.x*32, oy0 = blockIdx.y*32;
    const int tid = threadIdx.x;

    if (tid < CH*9) {
        int ci = tid / 9, k = tid % 9;
        int dy = k/3, dx = k - dy*3;
        int off = (b*CH + ci)*9 + dx*3 + dy;
        sW[tid] = make_float2(w1r[off], -w1i[off]);
    }
    for (int p = tid; p < 34*34; p += 256) {
        int yy = p/34, xx = p - 34*yy;
        int gy = oy0 + yy - 1, gx = ox0 + xx - 1;
        float2 vals[16];
        if ((unsigned)gy < 256u && (unsigned)gx < 256u) {
            size_t pb = (((size_t)b*256 + gy)*256 + gx)*32;
            uint4 hv[4], lv[4];
            const uint4* ph = (const uint4*)(in_hi + pb);
            const uint4* pl = (const uint4*)(in_lo + pb);
#pragma unroll
            for (int j = 0; j < 4; j++) { hv[j] = ph[j]; lv[j] = pl[j]; }
            const __nv_bfloat16* hb = (const __nv_bfloat16*)hv;
            const __nv_bfloat16* lb = (const __nv_bfloat16*)lv;
#pragma unroll
            for (int ci = 0; ci < 16; ci++) {
                float re = __bfloat162float(hb[ci])    + __bfloat162float(lb[ci]);
                float im = __bfloat162float(hb[ci+16]) + __bfloat162float(lb[ci+16]);
                vals[ci] = make_float2(re, im);
            }
        } else {
#pragma unroll
            for (int ci = 0; ci < 16; ci++) vals[ci] = make_float2(0.f, 0.f);
        }
#pragma unroll
        for (int ci = 0; ci < 16; ci++)
            sIn[ci*(34*34) + p] = vals[ci];
    }
    __syncthreads();

    const int qx = tid & 15, qy = tid >> 4;
    const int px0 = qx*2, py0 = qy*2;
    float ar[4] = {0.f,0.f,0.f,0.f}, ai[4] = {0.f,0.f,0.f,0.f};

#pragma unroll 1
    for (int ci = 0; ci < CH; ci++) {
        float2 p[4][4];
        const float2* base = sIn + ci*(34*34) + py0*34 + px0;
#pragma unroll
        for (int yy = 0; yy < 4; yy++)
#pragma unroll
            for (int xx = 0; xx < 4; xx++)
                p[yy][xx] = base[yy*34 + xx];
#pragma unroll
        for (int k = 0; k < 9; k++) {
            int dy = k/3, dx = k - dy*3;
            float2 w = sW[ci*9 + k];
#pragma unroll
            for (int iy = 0; iy < 2; iy++)
#pragma unroll
                for (int ix = 0; ix < 2; ix++) {
                    float2 x = p[dy+iy][dx+ix];
                    ar[iy*2+ix] = fmaf(w.x, x.x, fmaf(-w.y, x.y, ar[iy*2+ix]));
                    ai[iy*2+ix] = fmaf(w.x, x.y, fmaf( w.y, x.x, ai[iy*2+ix]));
                }
        }
    }
#pragma unroll
    for (int iy = 0; iy < 2; iy++) {
        int oy = oy0 + py0 + iy;
        int ox = ox0 + px0;
        *(float4*)(g_c1 + (size_t)b*GG + (size_t)oy*256 + ox) =
            make_float4(ar[iy*2+0], ai[iy*2+0], ar[iy*2+1], ai[iy*2+1]);
    }
}

// ---------------- forward fft2 with ifftshift on input ----------------
__global__ void fft_passA_kernel()
{
    __shared__ float2 bA[256], bB[256];
    const int m = blockIdx.x, b = blockIdx.y, t = threadIdx.x;
    const int msrc = (m + 128) & 255;
    const size_t base = (size_t)b*GG + (size_t)msrc*256;
    for (int k = t; k < 256; k += 128)
        bA[k] = g_c1[base + ((k + 128) & 255)];
    __syncthreads();
    fft256_block(bA, bB, t, -1.0f);
    for (int q = t; q < 256; q += 128)
        g_c2[(size_t)b*GG + (size_t)q*256 + m] = bA[q];
}

__global__ void fft_passB_kernel(float* __restrict__ out)
{
    __shared__ float2 bA[256], bB[256];
    const int q = blockIdx.x, b = blockIdx.y, t = threadIdx.x;
    const size_t base = (size_t)b*GG + (size_t)q*256;
    bA[t]     = g_c2[base + t];
    bA[t+128] = g_c2[base + t + 128];
    __syncthreads();
    fft256_block(bA, bB, t, -1.0f);
    for (int p = t; p < 256; p += 128)
        if (p < 127)
            out[((size_t)b*127 + p)*127 + q] = bA[p].x;
}

// ---------------- launch ----------------
extern "C" void kernel_launch(void* const* d_in, const int* in_sizes, int n_in,
                              void* d_out, int out_size)
{
    (void)in_sizes; (void)n_in; (void)out_size;
    const float* r   = (const float*)d_in[0];
    const float* w1r = (const float*)d_in[1];
    const float* w1i = (const float*)d_in[2];
    const float* w2r = (const float*)d_in[3];
    const float* w2i = (const float*)d_in[4];
    const float* w3r = (const float*)d_in[5];
    const float* w3i = (const float*)d_in[6];
    const float* wtr = (const float*)d_in[7];
    const float* wti = (const float*)d_in[8];
    float* out = (float*)d_out;

    void *pAh, *pAl, *pBh, *pBl, *pBw;
    cudaGetSymbolAddress(&pAh, g_Ahi);
    cudaGetSymbolAddress(&pAl, g_Alo);
    cudaGetSymbolAddress(&pBh, g_Bhi);
    cudaGetSymbolAddress(&pBl, g_Blo);
    cudaGetSymbolAddress(&pBw, g_Bw);
    __nv_bfloat16* Ah = (__nv_bfloat16*)pAh;
    __nv_bfloat16* Al = (__nv_bfloat16*)pAl;
    __nv_bfloat16* Bh = (__nv_bfloat16*)pBh;
    __nv_bfloat16* Bl = (__nv_bfloat16*)pBl;
    __nv_bfloat16* Bw = (__nv_bfloat16*)pBw;

    const int SMEMA1 = CH*34*34*(int)sizeof(float2);
    cudaFuncSetAttribute(conv16_mma<false>, cudaFuncAttributeMaxDynamicSharedMemorySize, SMEM_MMA);
    cudaFuncSetAttribute(conv16_mma<true >, cudaFuncAttributeMaxDynamicSharedMemorySize, SMEM_MMA);
    cudaFuncSetAttribute(conv_adj1_kernel,  cudaFuncAttributeMaxDynamicSharedMemorySize, SMEMA1);

    dim3 gfft(256, NB);
    ifft_passA_kernel<<<gfft, 128>>>(r);

    dim3 gwp(NB, 4);
    wprep_kernel<<<gwp, 256>>>(w2r, w2i, w3r, w3i);

    ifft_passB_kernel<<<gfft, 128>>>();

    dim3 gc1(8, 8, NB);
    conv1_kernel<<<gc1, 256>>>(w1r, w1i, Ah, Al);

    dim3 gconv(16, 16, NB);
    conv16_mma<false><<<gconv, 256, SMEM_MMA>>>(Ah, Al, Bh, Bl, Bw, 0, nullptr, nullptr);
    conv16_mma<true ><<<gconv, 256, SMEM_MMA>>>(Bh, Bl, Ah, Al, Bw, 1, wtr, wti);
    conv16_mma<false><<<gconv, 256, SMEM_MMA>>>(Ah, Al, Bh, Bl, Bw, 2, nullptr, nullptr);
    conv16_mma<false><<<gconv, 256, SMEM_MMA>>>(Bh, Bl, Ah, Al, Bw, 3, nullptr, nullptr);
    conv_adj1_kernel<<<gc1, 256, SMEMA1>>>(Ah, Al, w1r, w1i);

    fft_passA_kernel<<<gfft, 128>>>();
    dim3 gfftB(127, NB);
    fft_passB_kernel<<<gfftB, 128>>>(out);
}

// round 9
// speedup vs baseline: 1.0329x; 1.0270x over previous
#include <cuda_runtime.h>
#include <cuda_bf16.h>
#include <math.h>

#define NB 32
#define CH 16
#define G  256
#define GG (G*G)

#define XSTR 40
#define BSTR 40
#define TI   16
#define TH   18
#define XEL2 (TH*TH*XSTR)
#define BROWS (9*2*32)
#define SMEM_MMA ((2*XEL2 + BROWS*BSTR) * 2)   // 97,920 B

typedef unsigned int u32;

// ---------------- scratch ----------------
__device__ float  g_rhat[NB*GG];
__device__ float2 g_c1[NB*GG];
__device__ float2 g_c2[NB*GG];
__device__ __nv_bfloat16 g_Ahi[(size_t)NB*GG*32];
__device__ __nv_bfloat16 g_Alo[(size_t)NB*GG*32];
__device__ __nv_bfloat16 g_Bhi[(size_t)NB*GG*32];
__device__ __nv_bfloat16 g_Blo[(size_t)NB*GG*32];
__device__ __nv_bfloat16 g_Bw[4*NB*BROWS*32];

// ---------------- helpers ----------------
__device__ __forceinline__ u32 sptr(const void* p) {
    return (u32)__cvta_generic_to_shared(p);
}
__device__ __forceinline__ void ldmat4(u32* r, u32 addr) {
    asm volatile("ldmatrix.sync.aligned.m8n8.x4.shared.b16 {%0,%1,%2,%3}, [%4];"
        : "=r"(r[0]), "=r"(r[1]), "=r"(r[2]), "=r"(r[3]) : "r"(addr));
}
__device__ __forceinline__ void mma_bf16(float* d, const u32* a, const u32* b) {
    asm volatile("mma.sync.aligned.m16n8k16.row.col.f32.bf16.bf16.f32 "
        "{%0,%1,%2,%3}, {%4,%5,%6,%7}, {%8,%9}, {%0,%1,%2,%3};"
        : "+f"(d[0]), "+f"(d[1]), "+f"(d[2]), "+f"(d[3])
        : "r"(a[0]), "r"(a[1]), "r"(a[2]), "r"(a[3]), "r"(b[0]), "r"(b[1]));
}
__device__ __forceinline__ u32 pack_split(float a, float b, u32& lo_out) {
    __nv_bfloat16 ha = __float2bfloat16(a);
    __nv_bfloat16 hb = __float2bfloat16(b);
    float ra = a - __bfloat162float(ha);
    float rb = b - __bfloat162float(hb);
    __nv_bfloat162 H; H.x = ha; H.y = hb;
    __nv_bfloat162 L; L.x = __float2bfloat16(ra); L.y = __float2bfloat16(rb);
    lo_out = *(u32*)&L;
    return *(u32*)&H;
}
__device__ __forceinline__ int Lperm(int n) {
    return ((n & 7) >> 1) * 8 + ((n >> 3) << 1) + (n & 1);
}

// ---------------- 256-pt Stockham radix-2 FFT (sub-block of 128 threads) ----------------
__device__ __forceinline__ void fft256_block(float2* s0, float2* s1, int t, float dir)
{
    float2* src = s0; float2* dst = s1;
#pragma unroll
    for (int s = 0; s < 8; s++) {
        int Ns = 1 << s;
        int jm = t & (Ns - 1);
        float2 a = src[t];
        float2 b = src[t + 128];
        float ang = dir * 3.14159265358979323846f * (float)jm / (float)Ns;
        float sn, cs;
        __sincosf(ang, &sn, &cs);
        float2 bt = make_float2(b.x*cs - b.y*sn, b.x*sn + b.y*cs);
        int id = ((t >> s) << (s + 1)) | jm;
        dst[id]      = make_float2(a.x + bt.x, a.y + bt.y);
        dst[id + Ns] = make_float2(a.x - bt.x, a.y - bt.y);
        __syncthreads();
        float2* tt = src; src = dst; dst = tt;
    }
}

// ---------------- ifft2 pass A: 2 lines/block ----------------
__global__ void ifft_passA_kernel(const float* __restrict__ r)
{
    __shared__ float2 bA[2][256], bB[2][256];
    const int b = blockIdx.y, t = threadIdx.x;
    const int sub = t >> 7, tl = t & 127;
    const int m = blockIdx.x*2 + sub;

    const bool zrow = (m == 0 || m == 128);
    const float sm = (m < 128) ? 1.f : -1.f;
    const int   im = (m < 128) ? (m - 1) : (255 - m);
    const float* rrow = r + ((size_t)b*127 + (zrow ? 0 : im))*127;

#pragma unroll
    for (int k = 0; k < 2; k++) {
        int n = tl + k*128;
        float v = 0.f;
        if (!zrow && n != 0 && n != 128)
            v = (n < 128) ? rrow[n-1] : -rrow[255-n];
        bA[sub][n] = make_float2(sm * v, 0.f);
    }
    __syncthreads();
    fft256_block(bA[sub], bB[sub], tl, +1.0f);
    const float sc = 1.0f / 256.0f;
    for (int k = tl; k < 256; k += 128) {
        float2 v = bA[sub][k];
        g_c1[(size_t)b*GG + (size_t)((k+128)&255)*256 + m] = make_float2(v.x*sc, v.y*sc);
    }
}

// ---------------- ifft2 pass B: 2 lines/block ----------------
__global__ void ifft_passB_kernel()
{
    __shared__ float2 bA[2][256], bB[2][256];
    const int b = blockIdx.y, t = threadIdx.x;
    const int sub = t >> 7, tl = t & 127;
    const int vp = blockIdx.x*2 + sub;
    const size_t base = (size_t)b*GG + (size_t)vp*256;
    bA[sub][tl]     = g_c1[base + tl];
    bA[sub][tl+128] = g_c1[base + tl + 128];
    __syncthreads();
    fft256_block(bA[sub], bB[sub], tl, +1.0f);
    const float sc = 1.0f / 256.0f;
    for (int u = tl; u < 256; u += 128)
        g_rhat[(size_t)b*GG + (size_t)((u+128)&255)*256 + vp] = bA[sub][u].x * sc;
}

// ---------------- weight precompute ----------------
__global__ void wprep_kernel(const float* __restrict__ w2r, const float* __restrict__ w2i,
                             const float* __restrict__ w3r, const float* __restrict__ w3i)
{
    const int b = blockIdx.x, layer = blockIdx.y, tid = threadIdx.x;
    const float *wr, *wi; bool adj;
    if      (layer == 0) { wr = w2r; wi = w2i; adj = false; }
    else if (layer == 1) { wr = w3r; wi = w3i; adj = false; }
    else if (layer == 2) { wr = w3r; wi = w3i; adj = true;  }
    else                 { wr = w2r; wi = w2i; adj = true;  }
    __nv_bfloat16* dst = g_Bw + ((size_t)(layer*NB + b))*BROWS*32;

    for (int idx = tid; idx < 9*32*32; idx += 256) {
        int tap = idx >> 10;
        int n = (idx >> 5) & 31;
        int k = idx & 31;
        int dy = tap/3, dx = tap - 3*dy;
        int cn = Lperm(n);
        int co = cn & 15, ci = k & 15;
        float vr, vi;
        if (!adj) { int off = ((b*CH + co)*CH + ci)*9 + dy*3 + dx; vr = wr[off]; vi = wi[off]; }
        else      { int off = ((b*CH + ci)*CH + co)*9 + dx*3 + dy; vr = wr[off]; vi = -wi[off]; }
        float v = (cn < 16) ? ((k < 16) ? vr : -vi)
                            : ((k < 16) ? vi :  vr);
        __nv_bfloat16 h = __float2bfloat16(v);
        __nv_bfloat16 l = __float2bfloat16(v - __bfloat162float(h));
        dst[((tap*2 + 0)*32 + n)*32 + k] = h;
        dst[((tap*2 + 1)*32 + n)*32 + k] = l;
    }
}

// ---------------- conv1: thread-per-pixel, row blocks, coalesced stores ----------------
__global__ void __launch_bounds__(256) conv1_kernel(
    const float* __restrict__ w1r, const float* __restrict__ w1i,
    __nv_bfloat16* __restrict__ out_hi, __nv_bfloat16* __restrict__ out_lo)
{
    __shared__ float  srow[3][258];
    __shared__ float2 sW[CH*9];
    const int y = blockIdx.x, b = blockIdx.y;
    const int tid = threadIdx.x;

    for (int idx = tid; idx < 3*258; idx += 256) {
        int rr = idx / 258, cc = idx - rr*258;
        int gy = y - 1 + rr, gx = cc - 1;
        float v = 0.f;
        if ((unsigned)gy < 256u && (unsigned)gx < 256u)
            v = g_rhat[(size_t)b*GG + gy*256 + gx];
        srow[rr][cc] = v;
    }
    if (tid < CH*9) {
        int off = b*(CH*9) + tid;
        sW[tid] = make_float2(w1r[off], w1i[off]);
    }
    __syncthreads();

    const int x = tid;
    float p[3][3];
#pragma unroll
    for (int rr = 0; rr < 3; rr++)
#pragma unroll
        for (int cc = 0; cc < 3; cc++)
            p[rr][cc] = srow[rr][x + cc];

    float ar[16], ai[16];
#pragma unroll
    for (int c = 0; c < 16; c++) { ar[c] = 0.f; ai[c] = 0.f; }
#pragma unroll
    for (int k = 0; k < 9; k++) {
        int dy = k/3, dx = k - dy*3;
        float xv = p[dy][dx];
#pragma unroll
        for (int c = 0; c < 16; c++) {
            float2 w = sW[c*9 + k];
            ar[c] = fmaf(w.x, xv, ar[c]);
            ai[c] = fmaf(w.y, xv, ai[c]);
        }
    }
    // pixel layout: bf16[0..15] = re(ch 0..15), bf16[16..31] = im(ch 0..15)
    size_t pb = (((size_t)b*256 + y)*256 + x)*32;
    u32 h[16], l[16];
#pragma unroll
    for (int j = 0; j < 8; j++)
        h[j] = pack_split(ar[2*j], ar[2*j+1], l[j]);          // re pairs -> u32 j
#pragma unroll
    for (int j = 0; j < 8; j++)
        h[8+j] = pack_split(ai[2*j], ai[2*j+1], l[8+j]);      // im pairs -> u32 8+j
#pragma unroll
    for (int j = 0; j < 4; j++) {
        *(uint4*)(out_hi + pb + j*8) = make_uint4(h[4*j],h[4*j+1],h[4*j+2],h[4*j+3]);
        *(uint4*)(out_lo + pb + j*8) = make_uint4(l[4*j],l[4*j+1],l[4*j+2],l[4*j+3]);
    }
}

// ---------------- main complex 16->16 conv via mma.sync, 16x16 tile, 2 CTAs/SM ----------------
template<bool WT>
__global__ void __launch_bounds__(256, 2) conv16_mma(
    const __nv_bfloat16* __restrict__ in_hi, const __nv_bfloat16* __restrict__ in_lo,
    __nv_bfloat16* __restrict__ out_hi, __nv_bfloat16* __restrict__ out_lo,
    const __nv_bfloat16* __restrict__ Bw_base, int layer,
    const float* __restrict__ wtr, const float* __restrict__ wti)
{
    extern __shared__ __nv_bfloat16 sm[];
    __nv_bfloat16* sXhi = sm;
    __nv_bfloat16* sXlo = sm + XEL2;
    __nv_bfloat16* sB   = sm + 2*XEL2;

    const int b = blockIdx.z;
    const int ox0 = blockIdx.x*TI, oy0 = blockIdx.y*TI;
    const int tid = threadIdx.x;

    {
        const uint4* src = (const uint4*)(Bw_base + ((size_t)(layer*NB + b))*BROWS*32);
        for (int idx = tid; idx < BROWS*4; idx += 256) {
            int row = idx >> 2, j = idx & 3;
            *(uint4*)(sB + row*BSTR + j*8) = src[idx];
        }
    }
    for (int p = tid; p < TH*TH; p += 256) {
        int yy = p/TH, xx = p - TH*yy;
        int gy = oy0 + yy - 1, gx = ox0 + xx - 1;
        uint4 vh[4], vl[4];
        if ((unsigned)gy < 256u && (unsigned)gx < 256u) {
            size_t pb = (((size_t)b*256 + gy)*256 + gx)*32;
            const uint4* ph = (const uint4*)(in_hi + pb);
            const uint4* pl = (const uint4*)(in_lo + pb);
#pragma unroll
            for (int j = 0; j < 4; j++) { vh[j] = ph[j]; vl[j] = pl[j]; }
        } else {
            uint4 z = make_uint4(0,0,0,0);
#pragma unroll
            for (int j = 0; j < 4; j++) { vh[j] = z; vl[j] = z; }
        }
        uint4* dh = (uint4*)(sXhi + p*XSTR);
        uint4* dl = (uint4*)(sXlo + p*XSTR);
#pragma unroll
        for (int j = 0; j < 4; j++) { dh[j] = vh[j]; dl[j] = vl[j]; }
    }
    __syncthreads();

    const int w = tid >> 5, lane = tid & 31;
    const int mrow = ((lane>>3)&1)*8 + (lane&7);
    const int kofs = ((lane>>4)&1)*8;
    const u32 xhiB = sptr(sXhi), xloB = sptr(sXlo);
    const u32 sBB = sptr(sB);
    const u32 bLaneOff = ((lane & 7)*BSTR + (lane >> 3)*8) * 2;

    float acc[2][4][4];
#pragma unroll
    for (int mt = 0; mt < 2; mt++)
#pragma unroll
        for (int f = 0; f < 4; f++)
#pragma unroll
            for (int j = 0; j < 4; j++) acc[mt][f][j] = 0.f;

#pragma unroll 1
    for (int tap = 0; tap < 9; tap++) {
        int dy = tap/3, dx = tap - 3*dy;
        u32 bhi[2][4][2], blo[2][4][2];
#pragma unroll
        for (int f = 0; f < 4; f++) {
            u32 r[4];
            ldmat4(r, sBB + ((tap*2+0)*32 + f*8)*BSTR*2 + bLaneOff);
            bhi[0][f][0] = r[0]; bhi[0][f][1] = r[1];
            bhi[1][f][0] = r[2]; bhi[1][f][1] = r[3];
            ldmat4(r, sBB + ((tap*2+1)*32 + f*8)*BSTR*2 + bLaneOff);
            blo[0][f][0] = r[0]; blo[0][f][1] = r[1];
            blo[1][f][0] = r[2]; blo[1][f][1] = r[3];
        }
#pragma unroll
        for (int mt = 0; mt < 2; mt++) {
            int sy = w*2 + mt + dy;
            int sx = mrow + dx;
            u32 off = ((sy*TH + sx)*XSTR + kofs)*2;
#pragma unroll
            for (int k16 = 0; k16 < 2; k16++) {
                u32 ah[4], al[4];
                ldmat4(ah, xhiB + off + k16*32);
                ldmat4(al, xloB + off + k16*32);
#pragma unroll
                for (int f = 0; f < 4; f++) mma_bf16(acc[mt][f], ah, bhi[k16][f]);
#pragma unroll
                for (int f = 0; f < 4; f++) mma_bf16(acc[mt][f], ah, blo[k16][f]);
#pragma unroll
                for (int f = 0; f < 4; f++) mma_bf16(acc[mt][f], al, bhi[k16][f]);
            }
        }
    }

    const int rA = lane >> 2;
    const int q  = lane & 3;
    const bool isRe = (q < 2);
#pragma unroll
    for (int mt = 0; mt < 2; mt++) {
        int y = oy0 + w*2 + mt;
#pragma unroll
        for (int half = 0; half < 2; half++) {
            int x = ox0 + rA + half*8;
            size_t pb = (((size_t)b*256 + y)*256 + x)*32;
            if (!WT) {
                u32 h4[4], l4[4];
#pragma unroll
                for (int f = 0; f < 4; f++)
                    h4[f] = pack_split(acc[mt][f][half*2+0], acc[mt][f][half*2+1], l4[f]);
                *(uint4*)(out_hi + pb + q*8) = make_uint4(h4[0],h4[1],h4[2],h4[3]);
                *(uint4*)(out_lo + pb + q*8) = make_uint4(l4[0],l4[1],l4[2],l4[3]);
            } else {
                size_t wbase = (size_t)b*16*GG + (size_t)y*256 + x;
                u32 h4[4], l4[4];
#pragma unroll
                for (int f = 0; f < 4; f++) {
                    float o2[2];
#pragma unroll
                    for (int j = 0; j < 2; j++) {
                        float my = acc[mt][f][half*2+j];
                        float prt = __shfl_xor_sync(0xffffffffu, my, 2);
                        int c = (q & 1)*8 + 2*f + j;
                        float wre = wtr[wbase + (size_t)c*GG];
                        float wim = wti[wbase + (size_t)c*GG];
                        o2[j] = isRe ? (my*wre - prt*wim) : (my*wre + prt*wim);
                    }
                    h4[f] = pack_split(o2[0], o2[1], l4[f]);
                }
                *(uint4*)(out_hi + pb + q*8) = make_uint4(h4[0],h4[1],h4[2],h4[3]);
                *(uint4*)(out_lo + pb + q*8) = make_uint4(l4[0],l4[1],l4[2],l4[3]);
            }
        }
    }
}

// ---------------- conv 16->1 with adj(w1): 16x16 tile, thread-per-pixel ----------------
__global__ void __launch_bounds__(256) conv_adj1_kernel(
    const __nv_bfloat16* __restrict__ in_hi, const __nv_bfloat16* __restrict__ in_lo,
    const float* __restrict__ w1r, const float* __restrict__ w1i)
{
    __shared__ float2 sIn[CH][TH*TH];
    __shared__ float2 sW[CH*9];
    const int b  = blockIdx.z;
    const int ox0 = blockIdx.x*TI, oy0 = blockIdx.y*TI;
    const int tid = threadIdx.x;

    if (tid < CH*9) {
        int ci = tid / 9, k = tid % 9;
        int dy = k/3, dx = k - dy*3;
        int off = (b*CH + ci)*9 + dx*3 + dy;
        sW[tid] = make_float2(w1r[off], -w1i[off]);
    }
    for (int p = tid; p < TH*TH; p += 256) {
        int yy = p/TH, xx = p - TH*yy;
        int gy = oy0 + yy - 1, gx = ox0 + xx - 1;
        float2 vals[16];
        if ((unsigned)gy < 256u && (unsigned)gx < 256u) {
            size_t pb = (((size_t)b*256 + gy)*256 + gx)*32;
            uint4 hv[4], lv[4];
            const uint4* ph = (const uint4*)(in_hi + pb);
            const uint4* pl = (const uint4*)(in_lo + pb);
#pragma unroll
            for (int j = 0; j < 4; j++) { hv[j] = ph[j]; lv[j] = pl[j]; }
            const __nv_bfloat16* hb = (const __nv_bfloat16*)hv;
            const __nv_bfloat16* lb = (const __nv_bfloat16*)lv;
#pragma unroll
            for (int ci = 0; ci < 16; ci++) {
                float re = __bfloat162float(hb[ci])    + __bfloat162float(lb[ci]);
                float im = __bfloat162float(hb[ci+16]) + __bfloat162float(lb[ci+16]);
                vals[ci] = make_float2(re, im);
            }
        } else {
#pragma unroll
            for (int ci = 0; ci < 16; ci++) vals[ci] = make_float2(0.f, 0.f);
        }
#pragma unroll
        for (int ci = 0; ci < 16; ci++)
            sIn[ci][p] = vals[ci];
    }
    __syncthreads();

    const int xx = tid & 15, yy = tid >> 4;
    float ar = 0.f, ai = 0.f;
#pragma unroll 1
    for (int ci = 0; ci < CH; ci++) {
#pragma unroll
        for (int k = 0; k < 9; k++) {
            int dy = k/3, dx = k - dy*3;
            float2 w = sW[ci*9 + k];
            float2 x = sIn[ci][(yy+dy)*TH + xx+dx];
            ar = fmaf(w.x, x.x, fmaf(-w.y, x.y, ar));
            ai = fmaf(w.x, x.y, fmaf( w.y, x.x, ai));
        }
    }
    g_c1[(size_t)b*GG + (size_t)(oy0+yy)*256 + ox0+xx] = make_float2(ar, ai);
}

// ---------------- forward fft2 with ifftshift: 2 lines/block ----------------
__global__ void fft_passA_kernel()
{
    __shared__ float2 bA[2][256], bB[2][256];
    const int b = blockIdx.y, t = threadIdx.x;
    const int sub = t >> 7, tl = t & 127;
    const int m = blockIdx.x*2 + sub;
    const int msrc = (m + 128) & 255;
    const size_t base = (size_t)b*GG + (size_t)msrc*256;
    for (int k = tl; k < 256; k += 128)
        bA[sub][k] = g_c1[base + ((k + 128) & 255)];
    __syncthreads();
    fft256_block(bA[sub], bB[sub], tl, -1.0f);
    for (int q = tl; q < 256; q += 128)
        g_c2[(size_t)b*GG + (size_t)q*256 + m] = bA[sub][q];
}

__global__ void fft_passB_kernel(float* __restrict__ out)
{
    __shared__ float2 bA[2][256], bB[2][256];
    const int b = blockIdx.y, t = threadIdx.x;
    const int sub = t >> 7, tl = t & 127;
    const int q = blockIdx.x*2 + sub;          // 0..127; 127 valid lines
    const bool live = (q < 127);
    const size_t base = (size_t)b*GG + (size_t)(live ? q : 0)*256;
    bA[sub][tl]     = live ? g_c2[base + tl]       : make_float2(0.f,0.f);
    bA[sub][tl+128] = live ? g_c2[base + tl + 128] : make_float2(0.f,0.f);
    __syncthreads();
    fft256_block(bA[sub], bB[sub], tl, -1.0f);
    if (live)
        for (int p = tl; p < 256; p += 128)
            if (p < 127)
                out[((size_t)b*127 + p)*127 + q] = bA[sub][p].x;
}

// ---------------- launch ----------------
extern "C" void kernel_launch(void* const* d_in, const int* in_sizes, int n_in,
                              void* d_out, int out_size)
{
    (void)in_sizes; (void)n_in; (void)out_size;
    const float* r   = (const float*)d_in[0];
    const float* w1r = (const float*)d_in[1];
    const float* w1i = (const float*)d_in[2];
    const float* w2r = (const float*)d_in[3];
    const float* w2i = (const float*)d_in[4];
    const float* w3r = (const float*)d_in[5];
    const float* w3i = (const float*)d_in[6];
    const float* wtr = (const float*)d_in[7];
    const float* wti = (const float*)d_in[8];
    float* out = (float*)d_out;

    void *pAh, *pAl, *pBh, *pBl, *pBw;
    cudaGetSymbolAddress(&pAh, g_Ahi);
    cudaGetSymbolAddress(&pAl, g_Alo);
    cudaGetSymbolAddress(&pBh, g_Bhi);
    cudaGetSymbolAddress(&pBl, g_Blo);
    cudaGetSymbolAddress(&pBw, g_Bw);
    __nv_bfloat16* Ah = (__nv_bfloat16*)pAh;
    __nv_bfloat16* Al = (__nv_bfloat16*)pAl;
    __nv_bfloat16* Bh = (__nv_bfloat16*)pBh;
    __nv_bfloat16* Bl = (__nv_bfloat16*)pBl;
    __nv_bfloat16* Bw = (__nv_bfloat16*)pBw;

    cudaFuncSetAttribute(conv16_mma<false>, cudaFuncAttributeMaxDynamicSharedMemorySize, SMEM_MMA);
    cudaFuncSetAttribute(conv16_mma<true >, cudaFuncAttributeMaxDynamicSharedMemorySize, SMEM_MMA);

    dim3 gfft(128, NB);
    ifft_passA_kernel<<<gfft, 256>>>(r);

    dim3 gwp(NB, 4);
    wprep_kernel<<<gwp, 256>>>(w2r, w2i, w3r, w3i);

    ifft_passB_kernel<<<gfft, 256>>>();

    dim3 gc1(256, NB);
    conv1_kernel<<<gc1, 256>>>(w1r, w1i, Ah, Al);

    dim3 gconv(16, 16, NB);
    conv16_mma<false><<<gconv, 256, SMEM_MMA>>>(Ah, Al, Bh, Bl, Bw, 0, nullptr, nullptr);
    conv16_mma<true ><<<gconv, 256, SMEM_MMA>>>(Bh, Bl, Ah, Al, Bw, 1, wtr, wti);
    conv16_mma<false><<<gconv, 256, SMEM_MMA>>>(Ah, Al, Bh, Bl, Bw, 2, nullptr, nullptr);
    conv16_mma<false><<<gconv, 256, SMEM_MMA>>>(Bh, Bl, Ah, Al, Bw, 3, nullptr, nullptr);

    dim3 gadj(16, 16, NB);
    conv_adj1_kernel<<<gadj, 256>>>(Ah, Al, w1r, w1i);

    fft_passA_kernel<<<gfft, 256>>>();
    dim3 gfftB(64, NB);
    fft_passB_kernel<<<gfftB, 256>>>(out);
}

// round 10
// speedup vs baseline: 1.0516x; 1.0181x over previous
#include <cuda_runtime.h>
#include <cuda_bf16.h>
#include <math.h>

#define NB 32
#define CH 16
#define G  256
#define GG (G*G)

#define XSTR 40
#define BSTR 40
#define TI   16
#define TH   18
#define XEL2 (TH*TH*XSTR)
#define BROWS (9*2*32)
#define SMEM_MMA ((2*XEL2 + BROWS*BSTR) * 2)   // 97,920 B

#define LSTR 258   // padded FFT line stride (float2); 258*2 words ≡ 4 (mod 32) banks per line

typedef unsigned int u32;

// ---------------- scratch ----------------
__device__ float  g_rhat[NB*GG];
__device__ float2 g_c1[NB*GG];
__device__ float2 g_c2[NB*GG];
__device__ __nv_bfloat16 g_Ahi[(size_t)NB*GG*32];
__device__ __nv_bfloat16 g_Alo[(size_t)NB*GG*32];
__device__ __nv_bfloat16 g_Bhi[(size_t)NB*GG*32];
__device__ __nv_bfloat16 g_Blo[(size_t)NB*GG*32];
__device__ __nv_bfloat16 g_Bw[4*NB*BROWS*32];

// ---------------- helpers ----------------
__device__ __forceinline__ u32 sptr(const void* p) {
    return (u32)__cvta_generic_to_shared(p);
}
__device__ __forceinline__ void ldmat4(u32* r, u32 addr) {
    asm volatile("ldmatrix.sync.aligned.m8n8.x4.shared.b16 {%0,%1,%2,%3}, [%4];"
        : "=r"(r[0]), "=r"(r[1]), "=r"(r[2]), "=r"(r[3]) : "r"(addr));
}
__device__ __forceinline__ void mma_bf16(float* d, const u32* a, const u32* b) {
    asm volatile("mma.sync.aligned.m16n8k16.row.col.f32.bf16.bf16.f32 "
        "{%0,%1,%2,%3}, {%4,%5,%6,%7}, {%8,%9}, {%0,%1,%2,%3};"
        : "+f"(d[0]), "+f"(d[1]), "+f"(d[2]), "+f"(d[3])
        : "r"(a[0]), "r"(a[1]), "r"(a[2]), "r"(a[3]), "r"(b[0]), "r"(b[1]));
}
__device__ __forceinline__ u32 pack_split(float a, float b, u32& lo_out) {
    __nv_bfloat16 ha = __float2bfloat16(a);
    __nv_bfloat16 hb = __float2bfloat16(b);
    float ra = a - __bfloat162float(ha);
    float rb = b - __bfloat162float(hb);
    __nv_bfloat162 H; H.x = ha; H.y = hb;
    __nv_bfloat162 L; L.x = __float2bfloat16(ra); L.y = __float2bfloat16(rb);
    lo_out = *(u32*)&L;
    return *(u32*)&H;
}
__device__ __forceinline__ int Lperm(int n) {
    return ((n & 7) >> 1) * 8 + ((n >> 3) << 1) + (n & 1);
}

// ---------------- 256-pt FFT, 8 lines per block, 32 threads/line ----------------
// Data in s0 (per-line base pointer); result in s0. Block-wide syncs; all 8 lines lockstep.
// Caller must __syncthreads() between load and call.
__device__ __forceinline__ void fft256_multi(float2* s0, float2* s1, int lt, float dir)
{
    float2* src = s0; float2* dst = s1;
#pragma unroll
    for (int s = 0; s < 8; s++) {
        int Ns = 1 << s;
#pragma unroll
        for (int u = 0; u < 4; u++) {
            int j  = lt + 32*u;           // butterfly index 0..127
            int jm = j & (Ns - 1);
            float2 a = src[j];
            float2 b = src[j + 128];
            float ang = dir * 3.14159265358979323846f * (float)jm / (float)Ns;
            float sn, cs;
            __sincosf(ang, &sn, &cs);
            float2 bt = make_float2(b.x*cs - b.y*sn, b.x*sn + b.y*cs);
            int id = ((j >> s) << (s + 1)) | jm;
            dst[id]      = make_float2(a.x + bt.x, a.y + bt.y);
            dst[id + Ns] = make_float2(a.x - bt.x, a.y - bt.y);
        }
        __syncthreads();
        float2* tt = src; src = dst; dst = tt;
    }
}

// ---------------- ifft2 pass A: expand rows, FFT over n, transposed+shifted write ----------------
__global__ void ifft_passA_kernel(const float* __restrict__ r)
{
    __shared__ float2 sA[8*LSTR], sB[8*LSTR];
    const int b = blockIdx.y, tid = threadIdx.x;
    const int line = tid >> 5, lt = tid & 31;
    const int m = blockIdx.x*8 + line;

    const bool zrow = (m == 0 || m == 128);
    const float sm = (m < 128) ? 1.f : -1.f;
    const int   im = (m < 128) ? (m - 1) : (255 - m);
    const float* rrow = r + ((size_t)b*127 + (zrow ? 0 : im))*127;

    float2* s0 = sA + line*LSTR;
    float2* s1 = sB + line*LSTR;
#pragma unroll
    for (int u = 0; u < 8; u++) {
        int n = lt + 32*u;
        float v = 0.f;
        if (!zrow && n != 0 && n != 128)
            v = (n < 128) ? rrow[n-1] : -rrow[255-n];
        s0[n] = make_float2(sm * v, 0.f);
    }
    __syncthreads();
    fft256_multi(s0, s1, lt, +1.0f);

    // transposed write: g_c1[b][(v+128)&255][m0+mi], 8 consecutive m per 8 lanes
    const float sc = 1.0f / 256.0f;
    const int mi = tid & 7, vsub = tid >> 3;   // vsub 0..31
    const int m0 = blockIdx.x*8;
#pragma unroll
    for (int chunk = 0; chunk < 8; chunk++) {
        int v = chunk*32 + vsub;
        float2 val = sA[mi*LSTR + v];
        g_c1[(size_t)b*GG + (size_t)((v+128)&255)*256 + m0 + mi] =
            make_float2(val.x*sc, val.y*sc);
    }
}

// ---------------- ifft2 pass B: FFT over m (contiguous read), transposed real write ----------------
__global__ void ifft_passB_kernel()
{
    __shared__ float2 sA[8*LSTR], sB[8*LSTR];
    const int b = blockIdx.y, tid = threadIdx.x;
    const int line = tid >> 5, lt = tid & 31;
    const int vp = blockIdx.x*8 + line;
    const size_t base = (size_t)b*GG + (size_t)vp*256;

    float2* s0 = sA + line*LSTR;
    float2* s1 = sB + line*LSTR;
#pragma unroll
    for (int u = 0; u < 8; u++) {
        int n = lt + 32*u;
        s0[n] = g_c1[base + n];
    }
    __syncthreads();
    fft256_multi(s0, s1, lt, +1.0f);

    const float sc = 1.0f / 256.0f;
    const int vi = tid & 7, usub = tid >> 3;
    const int v0 = blockIdx.x*8;
#pragma unroll
    for (int chunk = 0; chunk < 8; chunk++) {
        int uu = chunk*32 + usub;
        g_rhat[(size_t)b*GG + (size_t)((uu+128)&255)*256 + v0 + vi] =
            sA[vi*LSTR + uu].x * sc;
    }
}

// ---------------- weight precompute ----------------
__global__ void wprep_kernel(const float* __restrict__ w2r, const float* __restrict__ w2i,
                             const float* __restrict__ w3r, const float* __restrict__ w3i)
{
    const int b = blockIdx.x, layer = blockIdx.y, tid = threadIdx.x;
    const float *wr, *wi; bool adj;
    if      (layer == 0) { wr = w2r; wi = w2i; adj = false; }
    else if (layer == 1) { wr = w3r; wi = w3i; adj = false; }
    else if (layer == 2) { wr = w3r; wi = w3i; adj = true;  }
    else                 { wr = w2r; wi = w2i; adj = true;  }
    __nv_bfloat16* dst = g_Bw + ((size_t)(layer*NB + b))*BROWS*32;

    for (int idx = tid; idx < 9*32*32; idx += 256) {
        int tap = idx >> 10;
        int n = (idx >> 5) & 31;
        int k = idx & 31;
        int dy = tap/3, dx = tap - 3*dy;
        int cn = Lperm(n);
        int co = cn & 15, ci = k & 15;
        float vr, vi;
        if (!adj) { int off = ((b*CH + co)*CH + ci)*9 + dy*3 + dx; vr = wr[off]; vi = wi[off]; }
        else      { int off = ((b*CH + ci)*CH + co)*9 + dx*3 + dy; vr = wr[off]; vi = -wi[off]; }
        float v = (cn < 16) ? ((k < 16) ? vr : -vi)
                            : ((k < 16) ? vi :  vr);
        __nv_bfloat16 h = __float2bfloat16(v);
        __nv_bfloat16 l = __float2bfloat16(v - __bfloat162float(h));
        dst[((tap*2 + 0)*32 + n)*32 + k] = h;
        dst[((tap*2 + 1)*32 + n)*32 + k] = l;
    }
}

// ---------------- conv1: thread-per-pixel, row blocks, coalesced stores ----------------
__global__ void __launch_bounds__(256) conv1_kernel(
    const float* __restrict__ w1r, const float* __restrict__ w1i,
    __nv_bfloat16* __restrict__ out_hi, __nv_bfloat16* __restrict__ out_lo)
{
    __shared__ float  srow[3][258];
    __shared__ float2 sW[CH*9];
    const int y = blockIdx.x, b = blockIdx.y;
    const int tid = threadIdx.x;

    for (int idx = tid; idx < 3*258; idx += 256) {
        int rr = idx / 258, cc = idx - rr*258;
        int gy = y - 1 + rr, gx = cc - 1;
        float v = 0.f;
        if ((unsigned)gy < 256u && (unsigned)gx < 256u)
            v = g_rhat[(size_t)b*GG + gy*256 + gx];
        srow[rr][cc] = v;
    }
    if (tid < CH*9) {
        int off = b*(CH*9) + tid;
        sW[tid] = make_float2(w1r[off], w1i[off]);
    }
    __syncthreads();

    const int x = tid;
    float p[3][3];
#pragma unroll
    for (int rr = 0; rr < 3; rr++)
#pragma unroll
        for (int cc = 0; cc < 3; cc++)
            p[rr][cc] = srow[rr][x + cc];

    float ar[16], ai[16];
#pragma unroll
    for (int c = 0; c < 16; c++) { ar[c] = 0.f; ai[c] = 0.f; }
#pragma unroll
    for (int k = 0; k < 9; k++) {
        int dy = k/3, dx = k - dy*3;
        float xv = p[dy][dx];
#pragma unroll
        for (int c = 0; c < 16; c++) {
            float2 w = sW[c*9 + k];
            ar[c] = fmaf(w.x, xv, ar[c]);
            ai[c] = fmaf(w.y, xv, ai[c]);
        }
    }
    size_t pb = (((size_t)b*256 + y)*256 + x)*32;
    u32 h[16], l[16];
#pragma unroll
    for (int j = 0; j < 8; j++)
        h[j] = pack_split(ar[2*j], ar[2*j+1], l[j]);
#pragma unroll
    for (int j = 0; j < 8; j++)
        h[8+j] = pack_split(ai[2*j], ai[2*j+1], l[8+j]);
#pragma unroll
    for (int j = 0; j < 4; j++) {
        *(uint4*)(out_hi + pb + j*8) = make_uint4(h[4*j],h[4*j+1],h[4*j+2],h[4*j+3]);
        *(uint4*)(out_lo + pb + j*8) = make_uint4(l[4*j],l[4*j+1],l[4*j+2],l[4*j+3]);
    }
}

// ---------------- main complex 16->16 conv via mma.sync, 16x16 tile, 2 CTAs/SM ----------------
template<bool WT>
__global__ void __launch_bounds__(256, 2) conv16_mma(
    const __nv_bfloat16* __restrict__ in_hi, const __nv_bfloat16* __restrict__ in_lo,
    __nv_bfloat16* __restrict__ out_hi, __nv_bfloat16* __restrict__ out_lo,
    const __nv_bfloat16* __restrict__ Bw_base, int layer,
    const float* __restrict__ wtr, const float* __restrict__ wti)
{
    extern __shared__ __nv_bfloat16 sm[];
    __nv_bfloat16* sXhi = sm;
    __nv_bfloat16* sXlo = sm + XEL2;
    __nv_bfloat16* sB   = sm + 2*XEL2;

    const int b = blockIdx.z;
    const int ox0 = blockIdx.x*TI, oy0 = blockIdx.y*TI;
    const int tid = threadIdx.x;

    {
        const uint4* src = (const uint4*)(Bw_base + ((size_t)(layer*NB + b))*BROWS*32);
        for (int idx = tid; idx < BROWS*4; idx += 256) {
            int row = idx >> 2, j = idx & 3;
            *(uint4*)(sB + row*BSTR + j*8) = src[idx];
        }
    }
    for (int p = tid; p < TH*TH; p += 256) {
        int yy = p/TH, xx = p - TH*yy;
        int gy = oy0 + yy - 1, gx = ox0 + xx - 1;
        uint4 vh[4], vl[4];
        if ((unsigned)gy < 256u && (unsigned)gx < 256u) {
            size_t pb = (((size_t)b*256 + gy)*256 + gx)*32;
            const uint4* ph = (const uint4*)(in_hi + pb);
            const uint4* pl = (const uint4*)(in_lo + pb);
#pragma unroll
            for (int j = 0; j < 4; j++) { vh[j] = ph[j]; vl[j] = pl[j]; }
        } else {
            uint4 z = make_uint4(0,0,0,0);
#pragma unroll
            for (int j = 0; j < 4; j++) { vh[j] = z; vl[j] = z; }
        }
        uint4* dh = (uint4*)(sXhi + p*XSTR);
        uint4* dl = (uint4*)(sXlo + p*XSTR);
#pragma unroll
        for (int j = 0; j < 4; j++) { dh[j] = vh[j]; dl[j] = vl[j]; }
    }
    __syncthreads();

    const int w = tid >> 5, lane = tid & 31;
    const int mrow = ((lane>>3)&1)*8 + (lane&7);
    const int kofs = ((lane>>4)&1)*8;
    const u32 xhiB = sptr(sXhi), xloB = sptr(sXlo);
    const u32 sBB = sptr(sB);
    const u32 bLaneOff = ((lane & 7)*BSTR + (lane >> 3)*8) * 2;

    float acc[2][4][4];
#pragma unroll
    for (int mt = 0; mt < 2; mt++)
#pragma unroll
        for (int f = 0; f < 4; f++)
#pragma unroll
            for (int j = 0; j < 4; j++) acc[mt][f][j] = 0.f;

#pragma unroll 1
    for (int tap = 0; tap < 9; tap++) {
        int dy = tap/3, dx = tap - 3*dy;
        u32 bhi[2][4][2], blo[2][4][2];
#pragma unroll
        for (int f = 0; f < 4; f++) {
            u32 r[4];
            ldmat4(r, sBB + ((tap*2+0)*32 + f*8)*BSTR*2 + bLaneOff);
            bhi[0][f][0] = r[0]; bhi[0][f][1] = r[1];
            bhi[1][f][0] = r[2]; bhi[1][f][1] = r[3];
            ldmat4(r, sBB + ((tap*2+1)*32 + f*8)*BSTR*2 + bLaneOff);
            blo[0][f][0] = r[0]; blo[0][f][1] = r[1];
            blo[1][f][0] = r[2]; blo[1][f][1] = r[3];
        }
#pragma unroll
        for (int mt = 0; mt < 2; mt++) {
            int sy = w*2 + mt + dy;
            int sx = mrow + dx;
            u32 off = ((sy*TH + sx)*XSTR + kofs)*2;
#pragma unroll
            for (int k16 = 0; k16 < 2; k16++) {
                u32 ah[4], al[4];
                ldmat4(ah, xhiB + off + k16*32);
                ldmat4(al, xloB + off + k16*32);
#pragma unroll
                for (int f = 0; f < 4; f++) mma_bf16(acc[mt][f], ah, bhi[k16][f]);
#pragma unroll
                for (int f = 0; f < 4; f++) mma_bf16(acc[mt][f], ah, blo[k16][f]);
#pragma unroll
                for (int f = 0; f < 4; f++) mma_bf16(acc[mt][f], al, bhi[k16][f]);
            }
        }
    }

    const int rA = lane >> 2;
    const int q  = lane & 3;
    const bool isRe = (q < 2);
#pragma unroll
    for (int mt = 0; mt < 2; mt++) {
        int y = oy0 + w*2 + mt;
#pragma unroll
        for (int half = 0; half < 2; half++) {
            int x = ox0 + rA + half*8;
            size_t pb = (((size_t)b*256 + y)*256 + x)*32;
            if (!WT) {
                u32 h4[4], l4[4];
#pragma unroll
                for (int f = 0; f < 4; f++)
                    h4[f] = pack_split(acc[mt][f][half*2+0], acc[mt][f][half*2+1], l4[f]);
                *(uint4*)(out_hi + pb + q*8) = make_uint4(h4[0],h4[1],h4[2],h4[3]);
                *(uint4*)(out_lo + pb + q*8) = make_uint4(l4[0],l4[1],l4[2],l4[3]);
            } else {
                size_t wbase = (size_t)b*16*GG + (size_t)y*256 + x;
                u32 h4[4], l4[4];
#pragma unroll
                for (int f = 0; f < 4; f++) {
                    float o2[2];
#pragma unroll
                    for (int j = 0; j < 2; j++) {
                        float my = acc[mt][f][half*2+j];
                        float prt = __shfl_xor_sync(0xffffffffu, my, 2);
                        int c = (q & 1)*8 + 2*f + j;
                        float wre = wtr[wbase + (size_t)c*GG];
                        float wim = wti[wbase + (size_t)c*GG];
                        o2[j] = isRe ? (my*wre - prt*wim) : (my*wre + prt*wim);
                    }
                    h4[f] = pack_split(o2[0], o2[1], l4[f]);
                }
                *(uint4*)(out_hi + pb + q*8) = make_uint4(h4[0],h4[1],h4[2],h4[3]);
                *(uint4*)(out_lo + pb + q*8) = make_uint4(l4[0],l4[1],l4[2],l4[3]);
            }
        }
    }
}

// ---------------- conv 16->1 with adj(w1): 16x16 tile, thread-per-pixel ----------------
__global__ void __launch_bounds__(256) conv_adj1_kernel(
    const __nv_bfloat16* __restrict__ in_hi, const __nv_bfloat16* __restrict__ in_lo,
    const float* __restrict__ w1r, const float* __restrict__ w1i)
{
    __shared__ float2 sIn[CH][TH*TH];
    __shared__ float2 sW[CH*9];
    const int b  = blockIdx.z;
    const int ox0 = blockIdx.x*TI, oy0 = blockIdx.y*TI;
    const int tid = threadIdx.x;

    if (tid < CH*9) {
        int ci = tid / 9, k = tid % 9;
        int dy = k/3, dx = k - dy*3;
        int off = (b*CH + ci)*9 + dx*3 + dy;
        sW[tid] = make_float2(w1r[off], -w1i[off]);
    }
    for (int p = tid; p < TH*TH; p += 256) {
        int yy = p/TH, xx = p - TH*yy;
        int gy = oy0 + yy - 1, gx = ox0 + xx - 1;
        float2 vals[16];
        if ((unsigned)gy < 256u && (unsigned)gx < 256u) {
            size_t pb = (((size_t)b*256 + gy)*256 + gx)*32;
            uint4 hv[4], lv[4];
            const uint4* ph = (const uint4*)(in_hi + pb);
            const uint4* pl = (const uint4*)(in_lo + pb);
#pragma unroll
            for (int j = 0; j < 4; j++) { hv[j] = ph[j]; lv[j] = pl[j]; }
            const __nv_bfloat16* hb = (const __nv_bfloat16*)hv;
            const __nv_bfloat16* lb = (const __nv_bfloat16*)lv;
#pragma unroll
            for (int ci = 0; ci < 16; ci++) {
                float re = __bfloat162float(hb[ci])    + __bfloat162float(lb[ci]);
                float im = __bfloat162float(hb[ci+16]) + __bfloat162float(lb[ci+16]);
                vals[ci] = make_float2(re, im);
            }
        } else {
#pragma unroll
            for (int ci = 0; ci < 16; ci++) vals[ci] = make_float2(0.f, 0.f);
        }
#pragma unroll
        for (int ci = 0; ci < 16; ci++)
            sIn[ci][p] = vals[ci];
    }
    __syncthreads();

    const int xx = tid & 15, yy = tid >> 4;
    float ar = 0.f, ai = 0.f;
#pragma unroll 1
    for (int ci = 0; ci < CH; ci++) {
#pragma unroll
        for (int k = 0; k < 9; k++) {
            int dy = k/3, dx = k - dy*3;
            float2 w = sW[ci*9 + k];
            float2 x = sIn[ci][(yy+dy)*TH + xx+dx];
            ar = fmaf(w.x, x.x, fmaf(-w.y, x.y, ar));
            ai = fmaf(w.x, x.y, fmaf( w.y, x.x, ai));
        }
    }
    g_c1[(size_t)b*GG + (size_t)(oy0+yy)*256 + ox0+xx] = make_float2(ar, ai);
}

// ---------------- forward fft2 pass A: ifftshift both dims on read, transposed write ----------------
__global__ void fft_passA_kernel()
{
    __shared__ float2 sA[8*LSTR], sB[8*LSTR];
    const int b = blockIdx.y, tid = threadIdx.x;
    const int line = tid >> 5, lt = tid & 31;
    const int m = blockIdx.x*8 + line;
    const int msrc = (m + 128) & 255;
    const size_t base = (size_t)b*GG + (size_t)msrc*256;

    float2* s0 = sA + line*LSTR;
    float2* s1 = sB + line*LSTR;
#pragma unroll
    for (int u = 0; u < 8; u++) {
        int k = lt + 32*u;
        s0[k] = g_c1[base + ((k + 128) & 255)];
    }
    __syncthreads();
    fft256_multi(s0, s1, lt, -1.0f);

    const int mi = tid & 7, qsub = tid >> 3;
    const int m0 = blockIdx.x*8;
#pragma unroll
    for (int chunk = 0; chunk < 8; chunk++) {
        int q = chunk*32 + qsub;
        g_c2[(size_t)b*GG + (size_t)q*256 + m0 + mi] = sA[mi*LSTR + q];
    }
}

// ---------------- forward fft2 pass B: contiguous read, transposed crop write ----------------
__global__ void fft_passB_kernel(float* __restrict__ out)
{
    __shared__ float2 sA[8*LSTR], sB[8*LSTR];
    const int b = blockIdx.y, tid = threadIdx.x;
    const int line = tid >> 5, lt = tid & 31;
    const int q = blockIdx.x*8 + line;        // 0..127; q=127 dead
    const bool live = (q < 127);
    const size_t base = (size_t)b*GG + (size_t)(live ? q : 0)*256;

    float2* s0 = sA + line*LSTR;
    float2* s1 = sB + line*LSTR;
#pragma unroll
    for (int u = 0; u < 8; u++) {
        int k = lt + 32*u;
        s0[k] = live ? g_c2[base + k] : make_float2(0.f, 0.f);
    }
    __syncthreads();
    fft256_multi(s0, s1, lt, -1.0f);

    const int qi = tid & 7, psub = tid >> 3;
    const int q0 = blockIdx.x*8;
#pragma unroll
    for (int chunk = 0; chunk < 8; chunk++) {
        int p = chunk*32 + psub;
        int qq = q0 + qi;
        if (p < 127 && qq < 127)
            out[((size_t)b*127 + p)*127 + qq] = sA[qi*LSTR + p].x;
    }
}

// ---------------- launch ----------------
extern "C" void kernel_launch(void* const* d_in, const int* in_sizes, int n_in,
                              void* d_out, int out_size)
{
    (void)in_sizes; (void)n_in; (void)out_size;
    const float* r   = (const float*)d_in[0];
    const float* w1r = (const float*)d_in[1];
    const float* w1i = (const float*)d_in[2];
    const float* w2r = (const float*)d_in[3];
    const float* w2i = (const float*)d_in[4];
    const float* w3r = (const float*)d_in[5];
    const float* w3i = (const float*)d_in[6];
    const float* wtr = (const float*)d_in[7];
    const float* wti = (const float*)d_in[8];
    float* out = (float*)d_out;

    void *pAh, *pAl, *pBh, *pBl, *pBw;
    cudaGetSymbolAddress(&pAh, g_Ahi);
    cudaGetSymbolAddress(&pAl, g_Alo);
    cudaGetSymbolAddress(&pBh, g_Bhi);
    cudaGetSymbolAddress(&pBl, g_Blo);
    cudaGetSymbolAddress(&pBw, g_Bw);
    __nv_bfloat16* Ah = (__nv_bfloat16*)pAh;
    __nv_bfloat16* Al = (__nv_bfloat16*)pAl;
    __nv_bfloat16* Bh = (__nv_bfloat16*)pBh;
    __nv_bfloat16* Bl = (__nv_bfloat16*)pBl;
    __nv_bfloat16* Bw = (__nv_bfloat16*)pBw;

    cudaFuncSetAttribute(conv16_mma<false>, cudaFuncAttributeMaxDynamicSharedMemorySize, SMEM_MMA);
    cudaFuncSetAttribute(conv16_mma<true >, cudaFuncAttributeMaxDynamicSharedMemorySize, SMEM_MMA);

    dim3 gfft(32, NB);
    ifft_passA_kernel<<<gfft, 256>>>(r);

    dim3 gwp(NB, 4);
    wprep_kernel<<<gwp, 256>>>(w2r, w2i, w3r, w3i);

    ifft_passB_kernel<<<gfft, 256>>>();

    dim3 gc1(256, NB);
    conv1_kernel<<<gc1, 256>>>(w1r, w1i, Ah, Al);

    dim3 gconv(16, 16, NB);
    conv16_mma<false><<<gconv, 256, SMEM_MMA>>>(Ah, Al, Bh, Bl, Bw, 0, nullptr, nullptr);
    conv16_mma<true ><<<gconv, 256, SMEM_MMA>>>(Bh, Bl, Ah, Al, Bw, 1, wtr, wti);
    conv16_mma<false><<<gconv, 256, SMEM_MMA>>>(Ah, Al, Bh, Bl, Bw, 2, nullptr, nullptr);
    conv16_mma<false><<<gconv, 256, SMEM_MMA>>>(Bh, Bl, Ah, Al, Bw, 3, nullptr, nullptr);

    dim3 gadj(16, 16, NB);
    conv_adj1_kernel<<<gadj, 256>>>(Ah, Al, w1r, w1i);

    fft_passA_kernel<<<gfft, 256>>>();
    dim3 gfftB(16, NB);
    fft_passB_kernel<<<gfftB, 256>>>(out);
}